// round 11
// baseline (speedup 1.0000x reference)
#include <cuda_runtime.h>
#include <cuda_bf16.h>
#include <math.h>
#include <stdint.h>

// ---------------- problem constants ----------------
#define NN      30000
#define IN_DIM  3000
#define DDIM    512
#define HID     512
#define OUTD    30
#define PREDD   20
#define DEG     10
#define EDGES   (NN*DEG)
#define NEG_SLOPE 0.2f

// ---------------- scratch ----------------
__device__ float g_x1 [NN*HID];
__device__ float g_h1 [NN*HID];
__device__ float g_x3 [NN*HID];
__device__ float g_h3 [NN*HID];
__device__ float g_h4 [NN*DDIM];
__device__ float g_a1s[NN];
__device__ float g_a1d[NN];
__device__ float g_alpha[EDGES];
__device__ float g_W2T[OUTD*HID];            // [30][512]
__device__ float g_bfused[HID];              // b_enc @ W1
__device__ float g_Wfused_r[IN_DIM*HID];     // round_tf32(W_enc @ W1), row-major
// fragment-permuted padded B operands: [NB][KB][4096]
__device__ float g_W1_p    [16*4 *4096];     // W1      K=512  N=512
__device__ float g_W1T_p   [16*4 *4096];     // W1^T    K=512  N=512
__device__ float g_Wdec_p  [16*24*4096];     // W_dec   K=512  N=3000(->3072)
__device__ float g_Wfused_p[94*4 *4096];     // Wfused  K=3000(->3008) N=512

// ---------------- tf32 rounding helpers ----------------
__device__ __forceinline__ float round_tf32f(float x) {
    uint32_t u;
    asm("cvt.rna.tf32.f32 %0, %1;" : "=r"(u) : "f"(x));
    return __uint_as_float(u);
}
__device__ __forceinline__ uint32_t f2tf32(float f) {
    uint32_t u;
    asm("cvt.rna.tf32.f32 %0, %1;" : "=r"(u) : "f"(f));
    return u;
}

// =====================================================================
// TF32 tensor-core GEMM: C[M,N] = A[M,K] @ B (+bias)
// B PRE-PERMUTED into mma fragment order (padded, bounds-check-free):
//   tile (nb,kt): offset = ks*1024 + tjj*64 + lane*2 + part
//   value = B[kt*32+ks*8+part*4+(lane&3)][nb*128+tjj*8+(lane>>2)]
// CTA 128x128, BK=32, 8 warps (2x4), warp tile 64x32.
// 3-stage cp.async.cg pipeline, one __syncthreads per k-iteration.
// ACVT: 1 = A raw fp32 -> cvt fragments post-LDS.
// FLAGS bit0 = ELU on output, bit1 = round output to tf32.
// =====================================================================
#define GA_STRIDE 36
#define BSTAGE 4096
#define STAGES 3
#define STAGE_FLOATS (128*GA_STRIDE + BSTAGE)
#define GSMEM_BYTES  (STAGES*STAGE_FLOATS*4)

__device__ __forceinline__ void cp16cg(uint32_t dst, const float* src, int sz) {
    asm volatile("cp.async.cg.shared.global [%0], [%1], 16, %2;\n"
                 :: "r"(dst), "l"(src), "r"(sz));
}

template<int ACVT, int FLAGS>
__global__ __launch_bounds__(256, 2) void tf32_gemm_kernel(
    const float* __restrict__ A, const float* __restrict__ Bp,
    const float* __restrict__ bias, float* __restrict__ C,
    int M, int N, int K, int KB)
{
    extern __shared__ float sm[];
    float* As = sm;                             // [STAGES][128][36]
    float* Bs = sm + STAGES * 128 * GA_STRIDE;  // [STAGES][4096]

    const int tid  = threadIdx.x;
    const int lane = tid & 31;
    const int warp = tid >> 5;          // 0..7
    const int wm   = warp >> 2;         // 0..1
    const int wn   = warp & 3;          // 0..3
    const int row0 = blockIdx.y * 128;
    const int col0 = blockIdx.x * 128;
    const int lr   = lane >> 2;         // 0..7
    const int lc   = lane & 3;          // 0..3

    float acc[4][4][4];
    #pragma unroll
    for (int i = 0; i < 4; i++)
        #pragma unroll
        for (int j = 0; j < 4; j++)
            #pragma unroll
            for (int q = 0; q < 4; q++) acc[i][j][q] = 0.f;

    const int nk = KB;
    const float* Btiles = Bp + (size_t)blockIdx.x * KB * BSTAGE;

    auto load_tile = [&](int stage, int kt) {
        const int k0 = kt << 5;
        float* Asb = As + stage * 128 * GA_STRIDE;
        float* Bsb = Bs + stage * BSTAGE;
        #pragma unroll
        for (int it = 0; it < 4; it++) {
            int idx = tid + it * 256;               // 0..1023
            int r = idx >> 3, c4 = (idx & 7) << 2;
            int gr = row0 + r, gc = k0 + c4;
            uint32_t dst = (uint32_t)__cvta_generic_to_shared(&Asb[r * GA_STRIDE + c4]);
            int sz = (gr < M && gc < K) ? 16 : 0;
            cp16cg(dst, A + (size_t)gr * K + gc, sz);
        }
        const float* Bt = Btiles + (size_t)kt * BSTAGE;
        #pragma unroll
        for (int it = 0; it < 4; it++) {
            int c4 = (tid + it * 256) << 2;         // float offset, 16B chunks
            uint32_t dst = (uint32_t)__cvta_generic_to_shared(&Bsb[c4]);
            cp16cg(dst, Bt + c4, 16);
        }
    };

    // prologue: 2 prefetches
    load_tile(0, 0);
    asm volatile("cp.async.commit_group;\n");
    if (nk > 1) load_tile(1, 1);
    asm volatile("cp.async.commit_group;\n");

    int stage = 0;
    for (int kt = 0; kt < nk; kt++) {
        asm volatile("cp.async.wait_group 1;\n");
        __syncthreads();

        if (kt + 2 < nk) load_tile((stage + 2 >= STAGES) ? stage + 2 - STAGES : stage + 2, kt + 2);
        asm volatile("cp.async.commit_group;\n");

        const float*    Asf = As + stage * 128 * GA_STRIDE;
        const uint32_t* Asb = (const uint32_t*)Asf;
        const float*    Bsb = Bs + stage * BSTAGE;

        #pragma unroll
        for (int ks = 0; ks < 4; ks++) {
            const int kk = ks << 3;
            uint32_t a[4][4];
            uint2 b[4];
            #pragma unroll
            for (int ti = 0; ti < 4; ti++) {
                int rb = wm * 64 + ti * 16 + lr;
                int kc = kk + lc;
                if (ACVT) {
                    a[ti][0] = f2tf32(Asf[rb * GA_STRIDE + kc]);
                    a[ti][1] = f2tf32(Asf[(rb + 8) * GA_STRIDE + kc]);
                    a[ti][2] = f2tf32(Asf[rb * GA_STRIDE + kc + 4]);
                    a[ti][3] = f2tf32(Asf[(rb + 8) * GA_STRIDE + kc + 4]);
                } else {
                    a[ti][0] = Asb[rb * GA_STRIDE + kc];
                    a[ti][1] = Asb[(rb + 8) * GA_STRIDE + kc];
                    a[ti][2] = Asb[rb * GA_STRIDE + kc + 4];
                    a[ti][3] = Asb[(rb + 8) * GA_STRIDE + kc + 4];
                }
            }
            #pragma unroll
            for (int tj = 0; tj < 4; tj++) {
                int tjj = wn * 4 + tj;
                b[tj] = *(const uint2*)(Bsb + (ks << 10) + (tjj << 6) + (lane << 1));
            }
            #pragma unroll
            for (int ti = 0; ti < 4; ti++)
                #pragma unroll
                for (int tj = 0; tj < 4; tj++) {
                    asm volatile(
                        "mma.sync.aligned.m16n8k8.row.col.f32.tf32.tf32.f32 "
                        "{%0,%1,%2,%3}, {%4,%5,%6,%7}, {%8,%9}, {%0,%1,%2,%3};\n"
                        : "+f"(acc[ti][tj][0]), "+f"(acc[ti][tj][1]),
                          "+f"(acc[ti][tj][2]), "+f"(acc[ti][tj][3])
                        : "r"(a[ti][0]), "r"(a[ti][1]), "r"(a[ti][2]), "r"(a[ti][3]),
                          "r"(b[tj].x), "r"(b[tj].y));
                }
        }
        stage = (stage + 1 >= STAGES) ? 0 : stage + 1;
    }

    // epilogue (float2 stores; c is even)
    constexpr bool DO_ELU   = (FLAGS & 1) != 0;
    constexpr bool DO_ROUND = (FLAGS & 2) != 0;
    #pragma unroll
    for (int ti = 0; ti < 4; ti++) {
        int r0 = row0 + wm * 64 + ti * 16 + lr;
        int r1 = r0 + 8;
        #pragma unroll
        for (int tj = 0; tj < 4; tj++) {
            int c = col0 + (wn * 4 + tj) * 8 + (lc << 1);
            float bv0 = 0.f, bv1 = 0.f;
            if (bias && c + 1 < N) {
                float2 bv = *(const float2*)(bias + c);
                bv0 = bv.x; bv1 = bv.y;
            } else if (bias && c < N) bv0 = bias[c];
            #pragma unroll
            for (int h = 0; h < 2; h++) {
                int r = h ? r1 : r0;
                if (r >= M) continue;
                float v0 = acc[ti][tj][h*2+0] + bv0;
                float v1 = acc[ti][tj][h*2+1] + bv1;
                if (DO_ELU) {
                    v0 = (v0 > 0.f) ? v0 : expm1f(v0);
                    v1 = (v1 > 0.f) ? v1 : expm1f(v1);
                }
                if (DO_ROUND) { v0 = round_tf32f(v0); v1 = round_tf32f(v1); }
                if (c + 1 < N) {
                    float2 st; st.x = v0; st.y = v1;
                    *(float2*)(C + (size_t)r * N + c) = st;
                } else if (c < N) {
                    C[(size_t)r * N + c] = v0;
                }
            }
        }
    }
}

// ---------------- B permutation prep ----------------
__global__ void perm_b_kernel(const float* __restrict__ src, float* __restrict__ dst,
                              int K, int N, int KB, int NB, int ld,
                              int trans, int do_round)
{
    int i = blockIdx.x * 256 + threadIdx.x;
    int total = KB * NB * 4096;
    if (i >= total) return;
    int tile = i >> 12, off = i & 4095;
    int kt = tile % KB, nb = tile / KB;
    int ks = off >> 10, rem = off & 1023;
    int tjj = rem >> 6, r2 = rem & 63;
    int lane = r2 >> 1, part = r2 & 1;
    int k = kt * 32 + ks * 8 + part * 4 + (lane & 3);
    int n = nb * 128 + tjj * 8 + (lane >> 2);
    float v = 0.f;
    if (k < K && n < N)
        v = trans ? src[(size_t)n * ld + k] : src[(size_t)k * ld + n];
    if (do_round) v = round_tf32f(v);
    dst[i] = v;
}

// ---------------- other prep ----------------
__global__ void transpose_kernel(const float* __restrict__ in,
                                 float* __restrict__ out, int R, int C)
{
    __shared__ float t[32][33];
    int c = blockIdx.x * 32 + threadIdx.x;
    int r = blockIdx.y * 32 + threadIdx.y;
    if (r < R && c < C) t[threadIdx.y][threadIdx.x] = in[r * C + c];
    __syncthreads();
    int r2 = blockIdx.x * 32 + threadIdx.y;
    int c2 = blockIdx.y * 32 + threadIdx.x;
    if (r2 < C && c2 < R) out[r2 * R + c2] = t[threadIdx.x][threadIdx.y];
}

__global__ void bias_fuse_kernel(const float* __restrict__ b_enc,
                                 const float* __restrict__ W1,
                                 float* __restrict__ bfused)
{
    int n = blockIdx.x * 128 + threadIdx.x;
    if (n >= HID) return;
    float s = 0.f;
    for (int k = 0; k < DDIM; k++) s += b_enc[k] * W1[(size_t)k * HID + n];
    bfused[n] = s;
}

// ---------------- h2 = h1 @ W2 (N=30) ----------------
#define W2T_SMEM (OUTD*HID*4)
__global__ __launch_bounds__(256) void h2_kernel(
    const float* __restrict__ h1, const float* __restrict__ W2T,
    float* __restrict__ h2)
{
    extern __shared__ float w[];
    const int tid = threadIdx.x;
    for (int i = tid; i < OUTD * HID; i += 256) w[i] = W2T[i];
    __syncthreads();
    const int wid = tid >> 5, lane = tid & 31;
    const int row = blockIdx.x * 8 + wid;
    if (row >= NN) return;
    float h[16];
    const float* hr = h1 + (size_t)row * HID;
    #pragma unroll
    for (int j = 0; j < 16; j++) h[j] = hr[lane + 32 * j];
    #pragma unroll
    for (int c = 0; c < OUTD; c++) {
        float s = 0.f;
        const float* wc = w + c * HID;
        #pragma unroll
        for (int j = 0; j < 16; j++) s += h[j] * wc[lane + 32 * j];
        #pragma unroll
        for (int o = 16; o > 0; o >>= 1) s += __shfl_xor_sync(0xffffffffu, s, o);
        if (lane == c) h2[(size_t)row * OUTD + c] = s;
    }
}

// ---------------- x3 = h2 @ W2^T (K=30) ----------------
__global__ __launch_bounds__(256) void x3_kernel(
    const float* __restrict__ h2, const float* __restrict__ W2T,
    float* __restrict__ x3)
{
    extern __shared__ float w[];
    const int tid = threadIdx.x;
    for (int i = tid; i < OUTD * HID; i += 256) w[i] = W2T[i];
    __syncthreads();
    const int wid = tid >> 5, lane = tid & 31;
    const int row = blockIdx.x * 8 + wid;
    if (row >= NN) return;
    float hc = (lane < OUTD) ? h2[(size_t)row * OUTD + lane] : 0.f;
    float acc[16];
    #pragma unroll
    for (int j = 0; j < 16; j++) acc[j] = 0.f;
    #pragma unroll
    for (int c = 0; c < OUTD; c++) {
        float b = __shfl_sync(0xffffffffu, hc, c);
        const float* wc = w + c * HID;
        #pragma unroll
        for (int j = 0; j < 16; j++) acc[j] += b * wc[lane + 32 * j];
    }
    float* xr = x3 + (size_t)row * HID;
    #pragma unroll
    for (int j = 0; j < 16; j++) xr[lane + 32 * j] = acc[j];
}

// ---------------- attention logits ----------------
__global__ void row_logits_kernel(const float* __restrict__ x1,
                                  const float* __restrict__ att_s,
                                  const float* __restrict__ att_d,
                                  float* __restrict__ a1s,
                                  float* __restrict__ a1d, int n)
{
    int row = blockIdx.x * 8 + threadIdx.y;
    if (row >= n) return;
    int lane = threadIdx.x;
    float s = 0.f, d = 0.f;
    const float* xr = x1 + (size_t)row * HID;
    #pragma unroll 4
    for (int k = lane; k < HID; k += 32) {
        float v = xr[k];
        s += v * att_s[k];
        d += v * att_d[k];
    }
    #pragma unroll
    for (int o = 16; o > 0; o >>= 1) {
        s += __shfl_down_sync(0xffffffffu, s, o);
        d += __shfl_down_sync(0xffffffffu, d, o);
    }
    if (lane == 0) { a1s[row] = s; a1d[row] = d; }
}

// ---------------- edge softmax ----------------
__global__ void alpha_kernel(const int* __restrict__ src,
                             const int* __restrict__ dst,
                             const float* __restrict__ a1s,
                             const float* __restrict__ a1d,
                             float* __restrict__ alpha, int n)
{
    int i = blockIdx.x * 256 + threadIdx.x;
    if (i >= n) return;
    float e[DEG];
    float m = -1e30f;
    #pragma unroll
    for (int j = 0; j < DEG; j++) {
        int eidx = i * DEG + j;
        float v = a1s[src[eidx]] + a1d[dst[eidx]];
        v = (v > 0.f) ? v : NEG_SLOPE * v;
        e[j] = v;
        m = fmaxf(m, v);
    }
    float sum = 0.f;
    #pragma unroll
    for (int j = 0; j < DEG; j++) { e[j] = __expf(e[j] - m); sum += e[j]; }
    float inv = 1.f / sum;
    #pragma unroll
    for (int j = 0; j < DEG; j++) alpha[i * DEG + j] = e[j] * inv;
}

// ---------------- weighted aggregation + ELU (+opt round) ----------------
__global__ __launch_bounds__(128) void agg_elu_kernel(
    const float* __restrict__ x, const int* __restrict__ src,
    const float* __restrict__ alpha, float* __restrict__ out, int round_out)
{
    int i = blockIdx.x;
    __shared__ int   ss[DEG];
    __shared__ float sa[DEG];
    if (threadIdx.x < DEG) {
        ss[threadIdx.x] = src[i * DEG + threadIdx.x];
        sa[threadIdx.x] = alpha[i * DEG + threadIdx.x];
    }
    __syncthreads();
    int c0 = threadIdx.x * 4;
    float a0 = 0.f, a1 = 0.f, a2 = 0.f, a3 = 0.f;
    #pragma unroll
    for (int j = 0; j < DEG; j++) {
        const float4 v = *(const float4*)&x[(size_t)ss[j] * HID + c0];
        float a = sa[j];
        a0 += a * v.x; a1 += a * v.y; a2 += a * v.z; a3 += a * v.w;
    }
    float4 r;
    r.x = (a0 > 0.f) ? a0 : expm1f(a0);
    r.y = (a1 > 0.f) ? a1 : expm1f(a1);
    r.z = (a2 > 0.f) ? a2 : expm1f(a2);
    r.w = (a3 > 0.f) ? a3 : expm1f(a3);
    if (round_out) {
        r.x = round_tf32f(r.x); r.y = round_tf32f(r.y);
        r.z = round_tf32f(r.z); r.w = round_tf32f(r.w);
    }
    *(float4*)&out[(size_t)i * HID + c0] = r;
}

// ---------------- prediction head ----------------
__global__ void pred_kernel(const float* __restrict__ h2,
                            const float* __restrict__ Wp,
                            const float* __restrict__ bp,
                            float* __restrict__ logp, int n)
{
    int i = blockIdx.x * 128 + threadIdx.x;
    if (i >= n) return;
    float h[OUTD];
    #pragma unroll
    for (int k = 0; k < OUTD; k++) h[k] = h2[(size_t)i * OUTD + k];
    float p[PREDD];
    float m = -1e30f;
    #pragma unroll
    for (int c = 0; c < PREDD; c++) {
        float s = bp[c];
        #pragma unroll
        for (int k = 0; k < OUTD; k++) s += h[k] * Wp[k * PREDD + c];
        p[c] = s;
        m = fmaxf(m, s);
    }
    float sum = 0.f;
    #pragma unroll
    for (int c = 0; c < PREDD; c++) sum += expf(p[c] - m);
    float lse = m + logf(sum);
    #pragma unroll
    for (int c = 0; c < PREDD; c++) logp[(size_t)i * PREDD + c] = p[c] - lse;
}

// ---------------- launch ----------------
static inline dim3 tf32_grid(int M, int N) {
    return dim3((N + 127) / 128, (M + 127) / 128);
}

extern "C" void kernel_launch(void* const* d_in, const int* in_sizes, int n_in,
                              void* d_out, int out_size)
{
    const float* features = (const float*)d_in[0];
    const int*   edge     = (const int*)  d_in[1];
    const float* W_enc    = (const float*)d_in[2];
    const float* b_enc    = (const float*)d_in[3];
    const float* W1       = (const float*)d_in[4];
    const float* att_src  = (const float*)d_in[5];
    const float* att_dst  = (const float*)d_in[6];
    const float* W2       = (const float*)d_in[7];
    const float* W_pred   = (const float*)d_in[8];
    const float* b_pred   = (const float*)d_in[9];
    const float* W_dec    = (const float*)d_in[10];
    const float* b_dec    = (const float*)d_in[11];

    const int* src = edge;
    const int* dst = edge + EDGES;

    float* out  = (float*)d_out;
    float* h2   = out;
    float* outm = out + (size_t)NN * OUTD;
    float* logp = out + (size_t)NN * OUTD + (size_t)NN * IN_DIM;

    float *x1, *h1, *x3, *h3, *h4, *a1s, *a1d, *alpha, *W2T;
    float *bfused, *Wfused_r, *W1_p, *W1T_p, *Wdec_p, *Wfused_p;
    cudaGetSymbolAddress((void**)&x1,    g_x1);
    cudaGetSymbolAddress((void**)&h1,    g_h1);
    cudaGetSymbolAddress((void**)&x3,    g_x3);
    cudaGetSymbolAddress((void**)&h3,    g_h3);
    cudaGetSymbolAddress((void**)&h4,    g_h4);
    cudaGetSymbolAddress((void**)&a1s,   g_a1s);
    cudaGetSymbolAddress((void**)&a1d,   g_a1d);
    cudaGetSymbolAddress((void**)&alpha, g_alpha);
    cudaGetSymbolAddress((void**)&W2T,   g_W2T);
    cudaGetSymbolAddress((void**)&bfused,   g_bfused);
    cudaGetSymbolAddress((void**)&Wfused_r, g_Wfused_r);
    cudaGetSymbolAddress((void**)&W1_p,     g_W1_p);
    cudaGetSymbolAddress((void**)&W1T_p,    g_W1T_p);
    cudaGetSymbolAddress((void**)&Wdec_p,   g_Wdec_p);
    cudaGetSymbolAddress((void**)&Wfused_p, g_Wfused_p);

    static int attr_set = 0;
    if (!attr_set) {
        cudaFuncSetAttribute(tf32_gemm_kernel<1,2>,
            cudaFuncAttributeMaxDynamicSharedMemorySize, GSMEM_BYTES);
        cudaFuncSetAttribute(tf32_gemm_kernel<1,0>,
            cudaFuncAttributeMaxDynamicSharedMemorySize, GSMEM_BYTES);
        cudaFuncSetAttribute(tf32_gemm_kernel<0,0>,
            cudaFuncAttributeMaxDynamicSharedMemorySize, GSMEM_BYTES);
        cudaFuncSetAttribute(tf32_gemm_kernel<0,3>,
            cudaFuncAttributeMaxDynamicSharedMemorySize, GSMEM_BYTES);
        cudaFuncSetAttribute(h2_kernel,
            cudaFuncAttributeMaxDynamicSharedMemorySize, W2T_SMEM);
        cudaFuncSetAttribute(x3_kernel,
            cudaFuncAttributeMaxDynamicSharedMemorySize, W2T_SMEM);
        attr_set = 1;
    }

    // ---- weight prep, ordered so launch #6 = the big fused GEMM (ncu -s 5 -c 1) ----
    // 1: permuted W1 (B of Wfused GEMM)
    perm_b_kernel<<<(16*4*4096 + 255)/256, 256>>>(W1, W1_p, DDIM, HID, 16, 4, HID, 0, 1);
    // 2: permuted W1^T (B of h4 GEMM)
    perm_b_kernel<<<(16*4*4096 + 255)/256, 256>>>(W1, W1T_p, HID, DDIM, 16, 4, HID, 1, 1);
    // 3: bfused
    bias_fuse_kernel<<<(HID + 127)/128, 128>>>(b_enc, W1, bfused);
    // 4: Wfused = round_tf32(W_enc @ W1)
    tf32_gemm_kernel<1,2><<<tf32_grid(IN_DIM, HID), 256, GSMEM_BYTES>>>(
        W_enc, W1_p, nullptr, Wfused_r, IN_DIM, HID, DDIM, 16);
    // 5: permute Wfused
    perm_b_kernel<<<(94*4*4096 + 255)/256, 256>>>(Wfused_r, Wfused_p, IN_DIM, HID, 94, 4, HID, 0, 0);
    // 6: *** x1 = features @ Wfused + bfused  (profiled by ncu) ***
    tf32_gemm_kernel<1,0><<<tf32_grid(NN, HID), 256, GSMEM_BYTES>>>(
        features, Wfused_p, bfused, x1, NN, HID, IN_DIM, 94);

    // remaining prep (independent of x1)
    perm_b_kernel<<<(16*24*4096 + 255)/256, 256>>>(W_dec, Wdec_p, DDIM, IN_DIM, 16, 24, IN_DIM, 0, 1);
    transpose_kernel<<<dim3((OUTD + 31)/32, (HID + 31)/32), dim3(32, 32)>>>(W2, W2T, HID, OUTD);

    // graph pipeline
    row_logits_kernel<<<(NN + 7)/8, dim3(32, 8)>>>(x1, att_src, att_dst, a1s, a1d, NN);
    alpha_kernel<<<(NN + 255)/256, 256>>>(src, dst, a1s, a1d, alpha, NN);
    agg_elu_kernel<<<NN, 128>>>(x1, src, alpha, h1, 0);
    h2_kernel<<<(NN + 7)/8, 256, W2T_SMEM>>>(h1, W2T, h2);
    pred_kernel<<<(NN + 127)/128, 128>>>(h2, W_pred, b_pred, logp, NN);
    x3_kernel<<<(NN + 7)/8, 256, W2T_SMEM>>>(h2, W2T, x3);
    agg_elu_kernel<<<NN, 128>>>(x3, src, alpha, h3, 1);
    // h4 = round_tf32(elu(h3 @ W1^T))
    tf32_gemm_kernel<0,3><<<tf32_grid(NN, DDIM), 256, GSMEM_BYTES>>>(
        h3, W1T_p, nullptr, h4, NN, DDIM, HID, 16);
    // out = h4 @ W_dec + b_dec
    tf32_gemm_kernel<0,0><<<tf32_grid(NN, IN_DIM), 256, GSMEM_BYTES>>>(
        h4, Wdec_p, b_dec, outm, NN, IN_DIM, DDIM, 16);
}

// round 12
// speedup vs baseline: 1.0322x; 1.0322x over previous
#include <cuda_runtime.h>
#include <cuda_bf16.h>
#include <math.h>
#include <stdint.h>

// ---------------- problem constants ----------------
#define NN      30000
#define IN_DIM  3000
#define DDIM    512
#define HID     512
#define OUTD    30
#define PREDD   20
#define DEG     10
#define EDGES   (NN*DEG)
#define NEG_SLOPE 0.2f

// ---------------- scratch ----------------
__device__ float g_x1 [NN*HID];
__device__ float g_h1 [NN*HID];
__device__ float g_x3 [NN*HID];
__device__ float g_h3 [NN*HID];
__device__ float g_h4 [NN*DDIM];
__device__ float g_a1s[NN];
__device__ float g_a1d[NN];
__device__ float g_alpha[EDGES];
__device__ float g_W2T[OUTD*HID];            // [30][512]
__device__ float g_bfused[HID];              // b_enc @ W1
__device__ float g_Wfused_r[IN_DIM*HID];     // round_tf32(W_enc @ W1), row-major
// fragment-permuted padded B operands: [NB][KB][4096]
__device__ float g_W1_p    [16*4 *4096];     // W1      K=512  N=512
__device__ float g_W1T_p   [16*4 *4096];     // W1^T    K=512  N=512
__device__ float g_Wdec_p  [16*24*4096];     // W_dec   K=512  N=3000(->3072)
__device__ float g_Wfused_p[94*4 *4096];     // Wfused  K=3000(->3008) N=512

// ---------------- tf32 rounding helpers ----------------
__device__ __forceinline__ float round_tf32f(float x) {
    uint32_t u;
    asm("cvt.rna.tf32.f32 %0, %1;" : "=r"(u) : "f"(x));
    return __uint_as_float(u);
}
__device__ __forceinline__ uint32_t f2tf32(float f) {
    uint32_t u;
    asm("cvt.rna.tf32.f32 %0, %1;" : "=r"(u) : "f"(f));
    return u;
}

// =====================================================================
// TF32 tensor-core GEMM (R10 config): C[M,N] = A[M,K] @ B (+bias)
// B PRE-PERMUTED into mma fragment order (padded, bounds-check-free).
// CTA 128x128, BK=32, 4 warps (2x2), warp tile 64x64.
// 3-stage cp.async.cg pipeline, one __syncthreads per k-iteration.
// ACVT: 1 = A raw fp32 -> cvt fragments post-LDS.
// FLAGS bit0 = ELU on output, bit1 = round output to tf32.
// =====================================================================
#define GA_STRIDE 36
#define BSTAGE 4096
#define STAGES 3
#define STAGE_FLOATS (128*GA_STRIDE + BSTAGE)
#define GSMEM_BYTES  (STAGES*STAGE_FLOATS*4)

__device__ __forceinline__ void cp16cg(uint32_t dst, const float* src, int sz) {
    asm volatile("cp.async.cg.shared.global [%0], [%1], 16, %2;\n"
                 :: "r"(dst), "l"(src), "r"(sz));
}

template<int ACVT, int FLAGS>
__global__ __launch_bounds__(128, 2) void tf32_gemm_kernel(
    const float* __restrict__ A, const float* __restrict__ Bp,
    const float* __restrict__ bias, float* __restrict__ C,
    int M, int N, int K, int KB)
{
    extern __shared__ float sm[];
    float* As = sm;                             // [STAGES][128][36]
    float* Bs = sm + STAGES * 128 * GA_STRIDE;  // [STAGES][4096]

    const int tid  = threadIdx.x;
    const int lane = tid & 31;
    const int warp = tid >> 5;          // 0..3
    const int wm   = warp >> 1;         // 0..1
    const int wn   = warp & 1;          // 0..1
    const int row0 = blockIdx.y * 128;
    const int col0 = blockIdx.x * 128;
    const int lr   = lane >> 2;         // 0..7
    const int lc   = lane & 3;          // 0..3

    float acc[4][8][4];
    #pragma unroll
    for (int i = 0; i < 4; i++)
        #pragma unroll
        for (int j = 0; j < 8; j++)
            #pragma unroll
            for (int q = 0; q < 4; q++) acc[i][j][q] = 0.f;

    const int nk = KB;
    const float* Btiles = Bp + (size_t)blockIdx.x * KB * BSTAGE;

    auto load_tile = [&](int stage, int kt) {
        const int k0 = kt << 5;
        float* Asb = As + stage * 128 * GA_STRIDE;
        float* Bsb = Bs + stage * BSTAGE;
        #pragma unroll
        for (int it = 0; it < 8; it++) {
            int idx = tid + it * 128;               // 0..1023
            int r = idx >> 3, c4 = (idx & 7) << 2;
            int gr = row0 + r, gc = k0 + c4;
            uint32_t dst = (uint32_t)__cvta_generic_to_shared(&Asb[r * GA_STRIDE + c4]);
            int sz = (gr < M && gc < K) ? 16 : 0;
            cp16cg(dst, A + (size_t)gr * K + gc, sz);
        }
        const float* Bt = Btiles + (size_t)kt * BSTAGE;
        #pragma unroll
        for (int it = 0; it < 8; it++) {
            int c4 = (tid + it * 128) << 2;         // float offset, 16B chunks
            uint32_t dst = (uint32_t)__cvta_generic_to_shared(&Bsb[c4]);
            cp16cg(dst, Bt + c4, 16);
        }
    };

    // prologue: 2 prefetches
    load_tile(0, 0);
    asm volatile("cp.async.commit_group;\n");
    if (nk > 1) load_tile(1, 1);
    asm volatile("cp.async.commit_group;\n");

    int stage = 0;
    for (int kt = 0; kt < nk; kt++) {
        asm volatile("cp.async.wait_group 1;\n");
        __syncthreads();

        if (kt + 2 < nk) load_tile((stage + 2 >= STAGES) ? stage + 2 - STAGES : stage + 2, kt + 2);
        asm volatile("cp.async.commit_group;\n");

        const float*    Asf = As + stage * 128 * GA_STRIDE;
        const uint32_t* Asb = (const uint32_t*)Asf;
        const float*    Bsb = Bs + stage * BSTAGE;

        #pragma unroll
        for (int ks = 0; ks < 4; ks++) {
            const int kk = ks << 3;
            uint32_t a[4][4];
            uint2 b[8];
            #pragma unroll
            for (int ti = 0; ti < 4; ti++) {
                int rb = wm * 64 + ti * 16 + lr;
                int kc = kk + lc;
                if (ACVT) {
                    a[ti][0] = f2tf32(Asf[rb * GA_STRIDE + kc]);
                    a[ti][1] = f2tf32(Asf[(rb + 8) * GA_STRIDE + kc]);
                    a[ti][2] = f2tf32(Asf[rb * GA_STRIDE + kc + 4]);
                    a[ti][3] = f2tf32(Asf[(rb + 8) * GA_STRIDE + kc + 4]);
                } else {
                    a[ti][0] = Asb[rb * GA_STRIDE + kc];
                    a[ti][1] = Asb[(rb + 8) * GA_STRIDE + kc];
                    a[ti][2] = Asb[rb * GA_STRIDE + kc + 4];
                    a[ti][3] = Asb[(rb + 8) * GA_STRIDE + kc + 4];
                }
            }
            #pragma unroll
            for (int tj = 0; tj < 8; tj++) {
                int tjj = wn * 8 + tj;
                b[tj] = *(const uint2*)(Bsb + (ks << 10) + (tjj << 6) + (lane << 1));
            }
            #pragma unroll
            for (int ti = 0; ti < 4; ti++)
                #pragma unroll
                for (int tj = 0; tj < 8; tj++) {
                    asm volatile(
                        "mma.sync.aligned.m16n8k8.row.col.f32.tf32.tf32.f32 "
                        "{%0,%1,%2,%3}, {%4,%5,%6,%7}, {%8,%9}, {%0,%1,%2,%3};\n"
                        : "+f"(acc[ti][tj][0]), "+f"(acc[ti][tj][1]),
                          "+f"(acc[ti][tj][2]), "+f"(acc[ti][tj][3])
                        : "r"(a[ti][0]), "r"(a[ti][1]), "r"(a[ti][2]), "r"(a[ti][3]),
                          "r"(b[tj].x), "r"(b[tj].y));
                }
        }
        stage = (stage + 1 >= STAGES) ? 0 : stage + 1;
    }

    // epilogue (float2 stores; c is even)
    constexpr bool DO_ELU   = (FLAGS & 1) != 0;
    constexpr bool DO_ROUND = (FLAGS & 2) != 0;
    #pragma unroll
    for (int ti = 0; ti < 4; ti++) {
        int r0 = row0 + wm * 64 + ti * 16 + lr;
        int r1 = r0 + 8;
        #pragma unroll
        for (int tj = 0; tj < 8; tj++) {
            int c = col0 + wn * 64 + tj * 8 + (lc << 1);
            float bv0 = 0.f, bv1 = 0.f;
            if (bias && c + 1 < N) {
                float2 bv = *(const float2*)(bias + c);
                bv0 = bv.x; bv1 = bv.y;
            } else if (bias && c < N) bv0 = bias[c];
            #pragma unroll
            for (int h = 0; h < 2; h++) {
                int r = h ? r1 : r0;
                if (r >= M) continue;
                float v0 = acc[ti][tj][h*2+0] + bv0;
                float v1 = acc[ti][tj][h*2+1] + bv1;
                if (DO_ELU) {
                    v0 = (v0 > 0.f) ? v0 : expm1f(v0);
                    v1 = (v1 > 0.f) ? v1 : expm1f(v1);
                }
                if (DO_ROUND) { v0 = round_tf32f(v0); v1 = round_tf32f(v1); }
                if (c + 1 < N) {
                    float2 st; st.x = v0; st.y = v1;
                    *(float2*)(C + (size_t)r * N + c) = st;
                } else if (c < N) {
                    C[(size_t)r * N + c] = v0;
                }
            }
        }
    }
}

// ---------------- B permutation prep ----------------
__global__ void perm_b_kernel(const float* __restrict__ src, float* __restrict__ dst,
                              int K, int N, int KB, int NB, int ld,
                              int trans, int do_round)
{
    int i = blockIdx.x * 256 + threadIdx.x;
    int total = KB * NB * 4096;
    if (i >= total) return;
    int tile = i >> 12, off = i & 4095;
    int kt = tile % KB, nb = tile / KB;
    int ks = off >> 10, rem = off & 1023;
    int tjj = rem >> 6, r2 = rem & 63;
    int lane = r2 >> 1, part = r2 & 1;
    int k = kt * 32 + ks * 8 + part * 4 + (lane & 3);
    int n = nb * 128 + tjj * 8 + (lane >> 2);
    float v = 0.f;
    if (k < K && n < N)
        v = trans ? src[(size_t)n * ld + k] : src[(size_t)k * ld + n];
    if (do_round) v = round_tf32f(v);
    dst[i] = v;
}

// ---------------- other prep ----------------
__global__ void transpose_kernel(const float* __restrict__ in,
                                 float* __restrict__ out, int R, int C)
{
    __shared__ float t[32][33];
    int c = blockIdx.x * 32 + threadIdx.x;
    int r = blockIdx.y * 32 + threadIdx.y;
    if (r < R && c < C) t[threadIdx.y][threadIdx.x] = in[r * C + c];
    __syncthreads();
    int r2 = blockIdx.x * 32 + threadIdx.y;
    int c2 = blockIdx.y * 32 + threadIdx.x;
    if (r2 < C && c2 < R) out[r2 * R + c2] = t[threadIdx.x][threadIdx.y];
}

__global__ void bias_fuse_kernel(const float* __restrict__ b_enc,
                                 const float* __restrict__ W1,
                                 float* __restrict__ bfused)
{
    int n = blockIdx.x * 128 + threadIdx.x;
    if (n >= HID) return;
    float s = 0.f;
    for (int k = 0; k < DDIM; k++) s += b_enc[k] * W1[(size_t)k * HID + n];
    bfused[n] = s;
}

// =====================================================================
// Fused head: per row, h2 = h1@W2, logp = log_softmax(h2@Wp + bp),
// x3 = h2@W2^T.  One pass over h1; W2T/Wp/bp cached in smem.
// Accumulation orders match the previous three separate kernels exactly.
// =====================================================================
#define HEAD_SMEM ((OUTD*HID + OUTD*PREDD + PREDD)*4)
__global__ __launch_bounds__(256) void h2px3_kernel(
    const float* __restrict__ h1, const float* __restrict__ W2T,
    const float* __restrict__ Wp, const float* __restrict__ bp,
    float* __restrict__ h2, float* __restrict__ logp, float* __restrict__ x3)
{
    extern __shared__ float sw[];
    float* w   = sw;                     // [30][512]
    float* wp  = sw + OUTD * HID;        // [30][20]
    float* bps = wp + OUTD * PREDD;      // [20]
    const int tid = threadIdx.x;
    for (int i = tid; i < OUTD * HID; i += 256) w[i] = W2T[i];
    for (int i = tid; i < OUTD * PREDD; i += 256) wp[i] = Wp[i];
    if (tid < PREDD) bps[tid] = bp[tid];
    __syncthreads();

    const int wid = tid >> 5, lane = tid & 31;
    const int row = blockIdx.x * 8 + wid;
    if (row >= NN) return;

    float h[16];
    const float* hr = h1 + (size_t)row * HID;
    #pragma unroll
    for (int j = 0; j < 16; j++) h[j] = hr[lane + 32 * j];

    float xacc[16];
    #pragma unroll
    for (int j = 0; j < 16; j++) xacc[j] = 0.f;
    float p[PREDD];
    #pragma unroll
    for (int c2 = 0; c2 < PREDD; c2++) p[c2] = bps[c2];

    #pragma unroll
    for (int c = 0; c < OUTD; c++) {
        const float* wc = w + c * HID;
        float wv[16];
        #pragma unroll
        for (int j = 0; j < 16; j++) wv[j] = wc[lane + 32 * j];
        float s = 0.f;
        #pragma unroll
        for (int j = 0; j < 16; j++) s += h[j] * wv[j];
        #pragma unroll
        for (int o = 16; o > 0; o >>= 1) s += __shfl_xor_sync(0xffffffffu, s, o);
        if (lane == c) h2[(size_t)row * OUTD + c] = s;
        #pragma unroll
        for (int j = 0; j < 16; j++) xacc[j] += s * wv[j];
        #pragma unroll
        for (int c2 = 0; c2 < PREDD; c2++) p[c2] += s * wp[c * PREDD + c2];
    }

    float* xr = x3 + (size_t)row * HID;
    #pragma unroll
    for (int j = 0; j < 16; j++) xr[lane + 32 * j] = xacc[j];

    float m = -1e30f;
    #pragma unroll
    for (int c2 = 0; c2 < PREDD; c2++) m = fmaxf(m, p[c2]);
    float sum = 0.f;
    #pragma unroll
    for (int c2 = 0; c2 < PREDD; c2++) sum += expf(p[c2] - m);
    float lse = m + logf(sum);
    #pragma unroll
    for (int c2 = 0; c2 < PREDD; c2++)
        if (lane == c2) logp[(size_t)row * PREDD + c2] = p[c2] - lse;
}

// ---------------- attention logits ----------------
__global__ void row_logits_kernel(const float* __restrict__ x1,
                                  const float* __restrict__ att_s,
                                  const float* __restrict__ att_d,
                                  float* __restrict__ a1s,
                                  float* __restrict__ a1d, int n)
{
    int row = blockIdx.x * 8 + threadIdx.y;
    if (row >= n) return;
    int lane = threadIdx.x;
    float s = 0.f, d = 0.f;
    const float* xr = x1 + (size_t)row * HID;
    #pragma unroll 4
    for (int k = lane; k < HID; k += 32) {
        float v = xr[k];
        s += v * att_s[k];
        d += v * att_d[k];
    }
    #pragma unroll
    for (int o = 16; o > 0; o >>= 1) {
        s += __shfl_down_sync(0xffffffffu, s, o);
        d += __shfl_down_sync(0xffffffffu, d, o);
    }
    if (lane == 0) { a1s[row] = s; a1d[row] = d; }
}

// ---------------- edge softmax ----------------
__global__ void alpha_kernel(const int* __restrict__ src,
                             const int* __restrict__ dst,
                             const float* __restrict__ a1s,
                             const float* __restrict__ a1d,
                             float* __restrict__ alpha, int n)
{
    int i = blockIdx.x * 256 + threadIdx.x;
    if (i >= n) return;
    float e[DEG];
    float m = -1e30f;
    #pragma unroll
    for (int j = 0; j < DEG; j++) {
        int eidx = i * DEG + j;
        float v = a1s[src[eidx]] + a1d[dst[eidx]];
        v = (v > 0.f) ? v : NEG_SLOPE * v;
        e[j] = v;
        m = fmaxf(m, v);
    }
    float sum = 0.f;
    #pragma unroll
    for (int j = 0; j < DEG; j++) { e[j] = __expf(e[j] - m); sum += e[j]; }
    float inv = 1.f / sum;
    #pragma unroll
    for (int j = 0; j < DEG; j++) alpha[i * DEG + j] = e[j] * inv;
}

// ---------------- weighted aggregation + ELU (+opt round) ----------------
__global__ __launch_bounds__(128) void agg_elu_kernel(
    const float* __restrict__ x, const int* __restrict__ src,
    const float* __restrict__ alpha, float* __restrict__ out, int round_out)
{
    int i = blockIdx.x;
    __shared__ int   ss[DEG];
    __shared__ float sa[DEG];
    if (threadIdx.x < DEG) {
        ss[threadIdx.x] = src[i * DEG + threadIdx.x];
        sa[threadIdx.x] = alpha[i * DEG + threadIdx.x];
    }
    __syncthreads();
    int c0 = threadIdx.x * 4;
    float a0 = 0.f, a1 = 0.f, a2 = 0.f, a3 = 0.f;
    #pragma unroll
    for (int j = 0; j < DEG; j++) {
        const float4 v = *(const float4*)&x[(size_t)ss[j] * HID + c0];
        float a = sa[j];
        a0 += a * v.x; a1 += a * v.y; a2 += a * v.z; a3 += a * v.w;
    }
    float4 r;
    r.x = (a0 > 0.f) ? a0 : expm1f(a0);
    r.y = (a1 > 0.f) ? a1 : expm1f(a1);
    r.z = (a2 > 0.f) ? a2 : expm1f(a2);
    r.w = (a3 > 0.f) ? a3 : expm1f(a3);
    if (round_out) {
        r.x = round_tf32f(r.x); r.y = round_tf32f(r.y);
        r.z = round_tf32f(r.z); r.w = round_tf32f(r.w);
    }
    *(float4*)&out[(size_t)i * HID + c0] = r;
}

// ---------------- launch ----------------
static inline dim3 tf32_grid(int M, int N) {
    return dim3((N + 127) / 128, (M + 127) / 128);
}

extern "C" void kernel_launch(void* const* d_in, const int* in_sizes, int n_in,
                              void* d_out, int out_size)
{
    const float* features = (const float*)d_in[0];
    const int*   edge     = (const int*)  d_in[1];
    const float* W_enc    = (const float*)d_in[2];
    const float* b_enc    = (const float*)d_in[3];
    const float* W1       = (const float*)d_in[4];
    const float* att_src  = (const float*)d_in[5];
    const float* att_dst  = (const float*)d_in[6];
    const float* W2       = (const float*)d_in[7];
    const float* W_pred   = (const float*)d_in[8];
    const float* b_pred   = (const float*)d_in[9];
    const float* W_dec    = (const float*)d_in[10];
    const float* b_dec    = (const float*)d_in[11];

    const int* src = edge;
    const int* dst = edge + EDGES;

    float* out  = (float*)d_out;
    float* h2   = out;
    float* outm = out + (size_t)NN * OUTD;
    float* logp = out + (size_t)NN * OUTD + (size_t)NN * IN_DIM;

    float *x1, *h1, *x3, *h3, *h4, *a1s, *a1d, *alpha, *W2T;
    float *bfused, *Wfused_r, *W1_p, *W1T_p, *Wdec_p, *Wfused_p;
    cudaGetSymbolAddress((void**)&x1,    g_x1);
    cudaGetSymbolAddress((void**)&h1,    g_h1);
    cudaGetSymbolAddress((void**)&x3,    g_x3);
    cudaGetSymbolAddress((void**)&h3,    g_h3);
    cudaGetSymbolAddress((void**)&h4,    g_h4);
    cudaGetSymbolAddress((void**)&a1s,   g_a1s);
    cudaGetSymbolAddress((void**)&a1d,   g_a1d);
    cudaGetSymbolAddress((void**)&alpha, g_alpha);
    cudaGetSymbolAddress((void**)&W2T,   g_W2T);
    cudaGetSymbolAddress((void**)&bfused,   g_bfused);
    cudaGetSymbolAddress((void**)&Wfused_r, g_Wfused_r);
    cudaGetSymbolAddress((void**)&W1_p,     g_W1_p);
    cudaGetSymbolAddress((void**)&W1T_p,    g_W1T_p);
    cudaGetSymbolAddress((void**)&Wdec_p,   g_Wdec_p);
    cudaGetSymbolAddress((void**)&Wfused_p, g_Wfused_p);

    static int attr_set = 0;
    if (!attr_set) {
        cudaFuncSetAttribute(tf32_gemm_kernel<1,2>,
            cudaFuncAttributeMaxDynamicSharedMemorySize, GSMEM_BYTES);
        cudaFuncSetAttribute(tf32_gemm_kernel<1,0>,
            cudaFuncAttributeMaxDynamicSharedMemorySize, GSMEM_BYTES);
        cudaFuncSetAttribute(tf32_gemm_kernel<0,0>,
            cudaFuncAttributeMaxDynamicSharedMemorySize, GSMEM_BYTES);
        cudaFuncSetAttribute(tf32_gemm_kernel<0,3>,
            cudaFuncAttributeMaxDynamicSharedMemorySize, GSMEM_BYTES);
        cudaFuncSetAttribute(h2px3_kernel,
            cudaFuncAttributeMaxDynamicSharedMemorySize, HEAD_SMEM);
        attr_set = 1;
    }

    // ---- weight prep, ordered so launch #6 = the big fused GEMM (ncu -s 5 -c 1) ----
    perm_b_kernel<<<(16*4*4096 + 255)/256, 256>>>(W1, W1_p, DDIM, HID, 16, 4, HID, 0, 1);
    perm_b_kernel<<<(16*4*4096 + 255)/256, 256>>>(W1, W1T_p, HID, DDIM, 16, 4, HID, 1, 1);
    bias_fuse_kernel<<<(HID + 127)/128, 128>>>(b_enc, W1, bfused);
    tf32_gemm_kernel<1,2><<<tf32_grid(IN_DIM, HID), 128, GSMEM_BYTES>>>(
        W_enc, W1_p, nullptr, Wfused_r, IN_DIM, HID, DDIM, 16);
    perm_b_kernel<<<(94*4*4096 + 255)/256, 256>>>(Wfused_r, Wfused_p, IN_DIM, HID, 94, 4, HID, 0, 0);
    // 6: *** x1 = features @ Wfused + bfused  (profiled by ncu) ***
    tf32_gemm_kernel<1,0><<<tf32_grid(NN, HID), 128, GSMEM_BYTES>>>(
        features, Wfused_p, bfused, x1, NN, HID, IN_DIM, 94);

    // remaining prep (independent of x1)
    perm_b_kernel<<<(16*24*4096 + 255)/256, 256>>>(W_dec, Wdec_p, DDIM, IN_DIM, 16, 24, IN_DIM, 0, 1);
    transpose_kernel<<<dim3((OUTD + 31)/32, (HID + 31)/32), dim3(32, 32)>>>(W2, W2T, HID, OUTD);

    // graph pipeline
    row_logits_kernel<<<(NN + 7)/8, dim3(32, 8)>>>(x1, att_src, att_dst, a1s, a1d, NN);
    alpha_kernel<<<(NN + 255)/256, 256>>>(src, dst, a1s, a1d, alpha, NN);
    agg_elu_kernel<<<NN, 128>>>(x1, src, alpha, h1, 0);
    // fused: h2 (out 0) + log-softmax head (out 2) + x3
    h2px3_kernel<<<(NN + 7)/8, 256, HEAD_SMEM>>>(h1, W2T, W_pred, b_pred, h2, logp, x3);
    agg_elu_kernel<<<NN, 128>>>(x3, src, alpha, h3, 1);
    // h4 = round_tf32(elu(h3 @ W1^T))
    tf32_gemm_kernel<0,3><<<tf32_grid(NN, DDIM), 128, GSMEM_BYTES>>>(
        h3, W1T_p, nullptr, h4, NN, DDIM, HID, 16);
    // out = h4 @ W_dec + b_dec
    tf32_gemm_kernel<0,0><<<tf32_grid(NN, IN_DIM), 128, GSMEM_BYTES>>>(
        h4, Wdec_p, b_dec, outm, NN, IN_DIM, DDIM, 16);
}

// round 13
// speedup vs baseline: 1.0347x; 1.0024x over previous
#include <cuda_runtime.h>
#include <cuda_bf16.h>
#include <math.h>
#include <stdint.h>

// ---------------- problem constants ----------------
#define NN      30000
#define IN_DIM  3000
#define DDIM    512
#define HID     512
#define OUTD    30
#define PREDD   20
#define DEG     10
#define EDGES   (NN*DEG)
#define NEG_SLOPE 0.2f

// ---------------- scratch ----------------
__device__ float g_x1 [NN*HID];
__device__ float g_h1 [NN*HID];
__device__ float g_x3 [NN*HID];
__device__ float g_h3 [NN*HID];
__device__ float g_h4 [NN*DDIM];
__device__ float g_a1s[NN];
__device__ float g_a1d[NN];
__device__ float g_alpha[EDGES];
__device__ float g_W2T[OUTD*HID];            // [30][512]
__device__ float g_bfused[HID];              // b_enc @ W1
__device__ float g_Wfused_r[IN_DIM*HID];     // round_tf32(W_enc @ W1), row-major
// fragment-permuted padded B operands: [NB][KB][4096]
__device__ float g_W1_p    [16*4 *4096];     // W1      K=512  N=512
__device__ float g_W1T_p   [16*4 *4096];     // W1^T    K=512  N=512
__device__ float g_Wdec_p  [16*24*4096];     // W_dec   K=512  N=3000(->3072)
__device__ float g_Wfused_p[94*4 *4096];     // Wfused  K=3000(->3008) N=512

// ---------------- tf32 rounding helpers ----------------
__device__ __forceinline__ float round_tf32f(float x) {
    uint32_t u;
    asm("cvt.rna.tf32.f32 %0, %1;" : "=r"(u) : "f"(x));
    return __uint_as_float(u);
}
__device__ __forceinline__ uint32_t f2tf32(float f) {
    uint32_t u;
    asm("cvt.rna.tf32.f32 %0, %1;" : "=r"(u) : "f"(f));
    return u;
}

// =====================================================================
// TF32 tensor-core GEMM: C[M,N] = A[M,K] @ B (+bias)
// B PRE-PERMUTED into mma fragment order (padded, bounds-check-free).
// CTA 128x128, BK=32, 4 warps (2x2), warp tile 64x64.
// 3-stage cp.async.cg pipeline, one __syncthreads per k-iteration.
// ACVT=0 path: software-pipelined fragment double-buffering in ks loop.
// ACVT=1 path: A raw fp32 -> cvt fragments post-LDS (reg-pressure-bound).
// FLAGS bit0 = ELU on output, bit1 = round output to tf32.
// =====================================================================
#define GA_STRIDE 36
#define BSTAGE 4096
#define STAGES 3
#define STAGE_FLOATS (128*GA_STRIDE + BSTAGE)
#define GSMEM_BYTES  (STAGES*STAGE_FLOATS*4)

__device__ __forceinline__ void cp16cg(uint32_t dst, const float* src, int sz) {
    asm volatile("cp.async.cg.shared.global [%0], [%1], 16, %2;\n"
                 :: "r"(dst), "l"(src), "r"(sz));
}

template<int ACVT, int FLAGS>
__global__ __launch_bounds__(128, 2) void tf32_gemm_kernel(
    const float* __restrict__ A, const float* __restrict__ Bp,
    const float* __restrict__ bias, float* __restrict__ C,
    int M, int N, int K, int KB)
{
    extern __shared__ float sm[];
    float* As = sm;                             // [STAGES][128][36]
    float* Bs = sm + STAGES * 128 * GA_STRIDE;  // [STAGES][4096]

    const int tid  = threadIdx.x;
    const int lane = tid & 31;
    const int warp = tid >> 5;          // 0..3
    const int wm   = warp >> 1;         // 0..1
    const int wn   = warp & 1;          // 0..1
    const int row0 = blockIdx.y * 128;
    const int col0 = blockIdx.x * 128;
    const int lr   = lane >> 2;         // 0..7
    const int lc   = lane & 3;          // 0..3

    float acc[4][8][4];
    #pragma unroll
    for (int i = 0; i < 4; i++)
        #pragma unroll
        for (int j = 0; j < 8; j++)
            #pragma unroll
            for (int q = 0; q < 4; q++) acc[i][j][q] = 0.f;

    const int nk = KB;
    const float* Btiles = Bp + (size_t)blockIdx.x * KB * BSTAGE;

    auto load_tile = [&](int stage, int kt) {
        const int k0 = kt << 5;
        float* Asb = As + stage * 128 * GA_STRIDE;
        float* Bsb = Bs + stage * BSTAGE;
        #pragma unroll
        for (int it = 0; it < 8; it++) {
            int idx = tid + it * 128;               // 0..1023
            int r = idx >> 3, c4 = (idx & 7) << 2;
            int gr = row0 + r, gc = k0 + c4;
            uint32_t dst = (uint32_t)__cvta_generic_to_shared(&Asb[r * GA_STRIDE + c4]);
            int sz = (gr < M && gc < K) ? 16 : 0;
            cp16cg(dst, A + (size_t)gr * K + gc, sz);
        }
        const float* Bt = Btiles + (size_t)kt * BSTAGE;
        #pragma unroll
        for (int it = 0; it < 8; it++) {
            int c4 = (tid + it * 128) << 2;         // float offset, 16B chunks
            uint32_t dst = (uint32_t)__cvta_generic_to_shared(&Bsb[c4]);
            cp16cg(dst, Bt + c4, 16);
        }
    };

    // prologue: 2 prefetches
    load_tile(0, 0);
    asm volatile("cp.async.commit_group;\n");
    if (nk > 1) load_tile(1, 1);
    asm volatile("cp.async.commit_group;\n");

    int stage = 0;
    for (int kt = 0; kt < nk; kt++) {
        asm volatile("cp.async.wait_group 1;\n");
        __syncthreads();

        if (kt + 2 < nk) load_tile((stage + 2 >= STAGES) ? stage + 2 - STAGES : stage + 2, kt + 2);
        asm volatile("cp.async.commit_group;\n");

        const float*    Asf = As + stage * 128 * GA_STRIDE;
        const uint32_t* Asb = (const uint32_t*)Asf;
        const float*    Bsb = Bs + stage * BSTAGE;

        if (ACVT) {
            // cvt-in-loop path (high reg pressure; no frag pipelining)
            #pragma unroll
            for (int ks = 0; ks < 4; ks++) {
                const int kk = ks << 3;
                uint32_t a[4][4];
                uint2 b[8];
                #pragma unroll
                for (int ti = 0; ti < 4; ti++) {
                    int rb = wm * 64 + ti * 16 + lr;
                    int kc = kk + lc;
                    a[ti][0] = f2tf32(Asf[rb * GA_STRIDE + kc]);
                    a[ti][1] = f2tf32(Asf[(rb + 8) * GA_STRIDE + kc]);
                    a[ti][2] = f2tf32(Asf[rb * GA_STRIDE + kc + 4]);
                    a[ti][3] = f2tf32(Asf[(rb + 8) * GA_STRIDE + kc + 4]);
                }
                #pragma unroll
                for (int tj = 0; tj < 8; tj++) {
                    int tjj = wn * 8 + tj;
                    b[tj] = *(const uint2*)(Bsb + (ks << 10) + (tjj << 6) + (lane << 1));
                }
                #pragma unroll
                for (int ti = 0; ti < 4; ti++)
                    #pragma unroll
                    for (int tj = 0; tj < 8; tj++) {
                        asm volatile(
                            "mma.sync.aligned.m16n8k8.row.col.f32.tf32.tf32.f32 "
                            "{%0,%1,%2,%3}, {%4,%5,%6,%7}, {%8,%9}, {%0,%1,%2,%3};\n"
                            : "+f"(acc[ti][tj][0]), "+f"(acc[ti][tj][1]),
                              "+f"(acc[ti][tj][2]), "+f"(acc[ti][tj][3])
                            : "r"(a[ti][0]), "r"(a[ti][1]), "r"(a[ti][2]), "r"(a[ti][3]),
                              "r"(b[tj].x), "r"(b[tj].y));
                    }
            }
        } else {
            // software-pipelined fragment double buffer
            uint32_t af[2][4][4];
            uint2    bf[2][8];
            // preload ks = 0
            #pragma unroll
            for (int ti = 0; ti < 4; ti++) {
                int rb = wm * 64 + ti * 16 + lr;
                af[0][ti][0] = Asb[rb * GA_STRIDE + lc];
                af[0][ti][1] = Asb[(rb + 8) * GA_STRIDE + lc];
                af[0][ti][2] = Asb[rb * GA_STRIDE + lc + 4];
                af[0][ti][3] = Asb[(rb + 8) * GA_STRIDE + lc + 4];
            }
            #pragma unroll
            for (int tj = 0; tj < 8; tj++) {
                int tjj = wn * 8 + tj;
                bf[0][tj] = *(const uint2*)(Bsb + (tjj << 6) + (lane << 1));
            }
            #pragma unroll
            for (int ks = 0; ks < 4; ks++) {
                const int cur = ks & 1, nxt = cur ^ 1;
                if (ks < 3) {
                    const int kk = (ks + 1) << 3;
                    #pragma unroll
                    for (int ti = 0; ti < 4; ti++) {
                        int rb = wm * 64 + ti * 16 + lr;
                        int kc = kk + lc;
                        af[nxt][ti][0] = Asb[rb * GA_STRIDE + kc];
                        af[nxt][ti][1] = Asb[(rb + 8) * GA_STRIDE + kc];
                        af[nxt][ti][2] = Asb[rb * GA_STRIDE + kc + 4];
                        af[nxt][ti][3] = Asb[(rb + 8) * GA_STRIDE + kc + 4];
                    }
                    #pragma unroll
                    for (int tj = 0; tj < 8; tj++) {
                        int tjj = wn * 8 + tj;
                        bf[nxt][tj] = *(const uint2*)(Bsb + ((ks + 1) << 10) + (tjj << 6) + (lane << 1));
                    }
                }
                #pragma unroll
                for (int ti = 0; ti < 4; ti++)
                    #pragma unroll
                    for (int tj = 0; tj < 8; tj++) {
                        asm volatile(
                            "mma.sync.aligned.m16n8k8.row.col.f32.tf32.tf32.f32 "
                            "{%0,%1,%2,%3}, {%4,%5,%6,%7}, {%8,%9}, {%0,%1,%2,%3};\n"
                            : "+f"(acc[ti][tj][0]), "+f"(acc[ti][tj][1]),
                              "+f"(acc[ti][tj][2]), "+f"(acc[ti][tj][3])
                            : "r"(af[cur][ti][0]), "r"(af[cur][ti][1]),
                              "r"(af[cur][ti][2]), "r"(af[cur][ti][3]),
                              "r"(bf[cur][tj].x), "r"(bf[cur][tj].y));
                    }
            }
        }
        stage = (stage + 1 >= STAGES) ? 0 : stage + 1;
    }

    // epilogue (float2 stores; c is even)
    constexpr bool DO_ELU   = (FLAGS & 1) != 0;
    constexpr bool DO_ROUND = (FLAGS & 2) != 0;
    #pragma unroll
    for (int ti = 0; ti < 4; ti++) {
        int r0 = row0 + wm * 64 + ti * 16 + lr;
        int r1 = r0 + 8;
        #pragma unroll
        for (int tj = 0; tj < 8; tj++) {
            int c = col0 + wn * 64 + tj * 8 + (lc << 1);
            float bv0 = 0.f, bv1 = 0.f;
            if (bias && c + 1 < N) {
                float2 bv = *(const float2*)(bias + c);
                bv0 = bv.x; bv1 = bv.y;
            } else if (bias && c < N) bv0 = bias[c];
            #pragma unroll
            for (int h = 0; h < 2; h++) {
                int r = h ? r1 : r0;
                if (r >= M) continue;
                float v0 = acc[ti][tj][h*2+0] + bv0;
                float v1 = acc[ti][tj][h*2+1] + bv1;
                if (DO_ELU) {
                    v0 = (v0 > 0.f) ? v0 : expm1f(v0);
                    v1 = (v1 > 0.f) ? v1 : expm1f(v1);
                }
                if (DO_ROUND) { v0 = round_tf32f(v0); v1 = round_tf32f(v1); }
                if (c + 1 < N) {
                    float2 st; st.x = v0; st.y = v1;
                    *(float2*)(C + (size_t)r * N + c) = st;
                } else if (c < N) {
                    C[(size_t)r * N + c] = v0;
                }
            }
        }
    }
}

// ---------------- B permutation prep ----------------
__global__ void perm_b_kernel(const float* __restrict__ src, float* __restrict__ dst,
                              int K, int N, int KB, int NB, int ld,
                              int trans, int do_round)
{
    int i = blockIdx.x * 256 + threadIdx.x;
    int total = KB * NB * 4096;
    if (i >= total) return;
    int tile = i >> 12, off = i & 4095;
    int kt = tile % KB, nb = tile / KB;
    int ks = off >> 10, rem = off & 1023;
    int tjj = rem >> 6, r2 = rem & 63;
    int lane = r2 >> 1, part = r2 & 1;
    int k = kt * 32 + ks * 8 + part * 4 + (lane & 3);
    int n = nb * 128 + tjj * 8 + (lane >> 2);
    float v = 0.f;
    if (k < K && n < N)
        v = trans ? src[(size_t)n * ld + k] : src[(size_t)k * ld + n];
    if (do_round) v = round_tf32f(v);
    dst[i] = v;
}

// ---------------- other prep ----------------
__global__ void transpose_kernel(const float* __restrict__ in,
                                 float* __restrict__ out, int R, int C)
{
    __shared__ float t[32][33];
    int c = blockIdx.x * 32 + threadIdx.x;
    int r = blockIdx.y * 32 + threadIdx.y;
    if (r < R && c < C) t[threadIdx.y][threadIdx.x] = in[r * C + c];
    __syncthreads();
    int r2 = blockIdx.x * 32 + threadIdx.y;
    int c2 = blockIdx.y * 32 + threadIdx.x;
    if (r2 < C && c2 < R) out[r2 * R + c2] = t[threadIdx.x][threadIdx.y];
}

__global__ void bias_fuse_kernel(const float* __restrict__ b_enc,
                                 const float* __restrict__ W1,
                                 float* __restrict__ bfused)
{
    int n = blockIdx.x * 128 + threadIdx.x;
    if (n >= HID) return;
    float s = 0.f;
    for (int k = 0; k < DDIM; k++) s += b_enc[k] * W1[(size_t)k * HID + n];
    bfused[n] = s;
}

// =====================================================================
// Fused head: h2 = h1@W2, logp = log_softmax(h2@Wp + bp), x3 = h2@W2^T.
// =====================================================================
#define HEAD_SMEM ((OUTD*HID + OUTD*PREDD + PREDD)*4)
__global__ __launch_bounds__(256) void h2px3_kernel(
    const float* __restrict__ h1, const float* __restrict__ W2T,
    const float* __restrict__ Wp, const float* __restrict__ bp,
    float* __restrict__ h2, float* __restrict__ logp, float* __restrict__ x3)
{
    extern __shared__ float sw[];
    float* w   = sw;                     // [30][512]
    float* wp  = sw + OUTD * HID;        // [30][20]
    float* bps = wp + OUTD * PREDD;      // [20]
    const int tid = threadIdx.x;
    for (int i = tid; i < OUTD * HID; i += 256) w[i] = W2T[i];
    for (int i = tid; i < OUTD * PREDD; i += 256) wp[i] = Wp[i];
    if (tid < PREDD) bps[tid] = bp[tid];
    __syncthreads();

    const int wid = tid >> 5, lane = tid & 31;
    const int row = blockIdx.x * 8 + wid;
    if (row >= NN) return;

    float h[16];
    const float* hr = h1 + (size_t)row * HID;
    #pragma unroll
    for (int j = 0; j < 16; j++) h[j] = hr[lane + 32 * j];

    float xacc[16];
    #pragma unroll
    for (int j = 0; j < 16; j++) xacc[j] = 0.f;
    float p[PREDD];
    #pragma unroll
    for (int c2 = 0; c2 < PREDD; c2++) p[c2] = bps[c2];

    #pragma unroll
    for (int c = 0; c < OUTD; c++) {
        const float* wc = w + c * HID;
        float wv[16];
        #pragma unroll
        for (int j = 0; j < 16; j++) wv[j] = wc[lane + 32 * j];
        float s = 0.f;
        #pragma unroll
        for (int j = 0; j < 16; j++) s += h[j] * wv[j];
        #pragma unroll
        for (int o = 16; o > 0; o >>= 1) s += __shfl_xor_sync(0xffffffffu, s, o);
        if (lane == c) h2[(size_t)row * OUTD + c] = s;
        #pragma unroll
        for (int j = 0; j < 16; j++) xacc[j] += s * wv[j];
        #pragma unroll
        for (int c2 = 0; c2 < PREDD; c2++) p[c2] += s * wp[c * PREDD + c2];
    }

    float* xr = x3 + (size_t)row * HID;
    #pragma unroll
    for (int j = 0; j < 16; j++) xr[lane + 32 * j] = xacc[j];

    float m = -1e30f;
    #pragma unroll
    for (int c2 = 0; c2 < PREDD; c2++) m = fmaxf(m, p[c2]);
    float sum = 0.f;
    #pragma unroll
    for (int c2 = 0; c2 < PREDD; c2++) sum += expf(p[c2] - m);
    float lse = m + logf(sum);
    #pragma unroll
    for (int c2 = 0; c2 < PREDD; c2++)
        if (lane == c2) logp[(size_t)row * PREDD + c2] = p[c2] - lse;
}

// ---------------- attention logits ----------------
__global__ void row_logits_kernel(const float* __restrict__ x1,
                                  const float* __restrict__ att_s,
                                  const float* __restrict__ att_d,
                                  float* __restrict__ a1s,
                                  float* __restrict__ a1d, int n)
{
    int row = blockIdx.x * 8 + threadIdx.y;
    if (row >= n) return;
    int lane = threadIdx.x;
    float s = 0.f, d = 0.f;
    const float* xr = x1 + (size_t)row * HID;
    #pragma unroll 4
    for (int k = lane; k < HID; k += 32) {
        float v = xr[k];
        s += v * att_s[k];
        d += v * att_d[k];
    }
    #pragma unroll
    for (int o = 16; o > 0; o >>= 1) {
        s += __shfl_down_sync(0xffffffffu, s, o);
        d += __shfl_down_sync(0xffffffffu, d, o);
    }
    if (lane == 0) { a1s[row] = s; a1d[row] = d; }
}

// ---------------- edge softmax ----------------
__global__ void alpha_kernel(const int* __restrict__ src,
                             const int* __restrict__ dst,
                             const float* __restrict__ a1s,
                             const float* __restrict__ a1d,
                             float* __restrict__ alpha, int n)
{
    int i = blockIdx.x * 256 + threadIdx.x;
    if (i >= n) return;
    float e[DEG];
    float m = -1e30f;
    #pragma unroll
    for (int j = 0; j < DEG; j++) {
        int eidx = i * DEG + j;
        float v = a1s[src[eidx]] + a1d[dst[eidx]];
        v = (v > 0.f) ? v : NEG_SLOPE * v;
        e[j] = v;
        m = fmaxf(m, v);
    }
    float sum = 0.f;
    #pragma unroll
    for (int j = 0; j < DEG; j++) { e[j] = __expf(e[j] - m); sum += e[j]; }
    float inv = 1.f / sum;
    #pragma unroll
    for (int j = 0; j < DEG; j++) alpha[i * DEG + j] = e[j] * inv;
}

// ---------------- weighted aggregation + ELU (+opt round) ----------------
__global__ __launch_bounds__(128) void agg_elu_kernel(
    const float* __restrict__ x, const int* __restrict__ src,
    const float* __restrict__ alpha, float* __restrict__ out, int round_out)
{
    int i = blockIdx.x;
    __shared__ int   ss[DEG];
    __shared__ float sa[DEG];
    if (threadIdx.x < DEG) {
        ss[threadIdx.x] = src[i * DEG + threadIdx.x];
        sa[threadIdx.x] = alpha[i * DEG + threadIdx.x];
    }
    __syncthreads();
    int c0 = threadIdx.x * 4;
    float a0 = 0.f, a1 = 0.f, a2 = 0.f, a3 = 0.f;
    #pragma unroll
    for (int j = 0; j < DEG; j++) {
        const float4 v = *(const float4*)&x[(size_t)ss[j] * HID + c0];
        float a = sa[j];
        a0 += a * v.x; a1 += a * v.y; a2 += a * v.z; a3 += a * v.w;
    }
    float4 r;
    r.x = (a0 > 0.f) ? a0 : expm1f(a0);
    r.y = (a1 > 0.f) ? a1 : expm1f(a1);
    r.z = (a2 > 0.f) ? a2 : expm1f(a2);
    r.w = (a3 > 0.f) ? a3 : expm1f(a3);
    if (round_out) {
        r.x = round_tf32f(r.x); r.y = round_tf32f(r.y);
        r.z = round_tf32f(r.z); r.w = round_tf32f(r.w);
    }
    *(float4*)&out[(size_t)i * HID + c0] = r;
}

// ---------------- launch ----------------
static inline dim3 tf32_grid(int M, int N) {
    return dim3((N + 127) / 128, (M + 127) / 128);
}

extern "C" void kernel_launch(void* const* d_in, const int* in_sizes, int n_in,
                              void* d_out, int out_size)
{
    const float* features = (const float*)d_in[0];
    const int*   edge     = (const int*)  d_in[1];
    const float* W_enc    = (const float*)d_in[2];
    const float* b_enc    = (const float*)d_in[3];
    const float* W1       = (const float*)d_in[4];
    const float* att_src  = (const float*)d_in[5];
    const float* att_dst  = (const float*)d_in[6];
    const float* W2       = (const float*)d_in[7];
    const float* W_pred   = (const float*)d_in[8];
    const float* b_pred   = (const float*)d_in[9];
    const float* W_dec    = (const float*)d_in[10];
    const float* b_dec    = (const float*)d_in[11];

    const int* src = edge;
    const int* dst = edge + EDGES;

    float* out  = (float*)d_out;
    float* h2   = out;
    float* outm = out + (size_t)NN * OUTD;
    float* logp = out + (size_t)NN * OUTD + (size_t)NN * IN_DIM;

    float *x1, *h1, *x3, *h3, *h4, *a1s, *a1d, *alpha, *W2T;
    float *bfused, *Wfused_r, *W1_p, *W1T_p, *Wdec_p, *Wfused_p;
    cudaGetSymbolAddress((void**)&x1,    g_x1);
    cudaGetSymbolAddress((void**)&h1,    g_h1);
    cudaGetSymbolAddress((void**)&x3,    g_x3);
    cudaGetSymbolAddress((void**)&h3,    g_h3);
    cudaGetSymbolAddress((void**)&h4,    g_h4);
    cudaGetSymbolAddress((void**)&a1s,   g_a1s);
    cudaGetSymbolAddress((void**)&a1d,   g_a1d);
    cudaGetSymbolAddress((void**)&alpha, g_alpha);
    cudaGetSymbolAddress((void**)&W2T,   g_W2T);
    cudaGetSymbolAddress((void**)&bfused,   g_bfused);
    cudaGetSymbolAddress((void**)&Wfused_r, g_Wfused_r);
    cudaGetSymbolAddress((void**)&W1_p,     g_W1_p);
    cudaGetSymbolAddress((void**)&W1T_p,    g_W1T_p);
    cudaGetSymbolAddress((void**)&Wdec_p,   g_Wdec_p);
    cudaGetSymbolAddress((void**)&Wfused_p, g_Wfused_p);

    static int attr_set = 0;
    if (!attr_set) {
        cudaFuncSetAttribute(tf32_gemm_kernel<1,2>,
            cudaFuncAttributeMaxDynamicSharedMemorySize, GSMEM_BYTES);
        cudaFuncSetAttribute(tf32_gemm_kernel<1,0>,
            cudaFuncAttributeMaxDynamicSharedMemorySize, GSMEM_BYTES);
        cudaFuncSetAttribute(tf32_gemm_kernel<0,0>,
            cudaFuncAttributeMaxDynamicSharedMemorySize, GSMEM_BYTES);
        cudaFuncSetAttribute(tf32_gemm_kernel<0,3>,
            cudaFuncAttributeMaxDynamicSharedMemorySize, GSMEM_BYTES);
        cudaFuncSetAttribute(h2px3_kernel,
            cudaFuncAttributeMaxDynamicSharedMemorySize, HEAD_SMEM);
        attr_set = 1;
    }

    // ---- weight prep, ordered so launch #6 = big GEMM, then dec is deep ----
    perm_b_kernel<<<(16*4*4096 + 255)/256, 256>>>(W1, W1_p, DDIM, HID, 16, 4, HID, 0, 1);
    perm_b_kernel<<<(16*4*4096 + 255)/256, 256>>>(W1, W1T_p, HID, DDIM, 16, 4, HID, 1, 1);
    bias_fuse_kernel<<<(HID + 127)/128, 128>>>(b_enc, W1, bfused);
    tf32_gemm_kernel<1,2><<<tf32_grid(IN_DIM, HID), 128, GSMEM_BYTES>>>(
        W_enc, W1_p, nullptr, Wfused_r, IN_DIM, HID, DDIM, 16);
    perm_b_kernel<<<(94*4*4096 + 255)/256, 256>>>(Wfused_r, Wfused_p, IN_DIM, HID, 94, 4, HID, 0, 0);
    // 6: x1 = features @ Wfused + bfused   [30000,512] K=3000
    tf32_gemm_kernel<1,0><<<tf32_grid(NN, HID), 128, GSMEM_BYTES>>>(
        features, Wfused_p, bfused, x1, NN, HID, IN_DIM, 94);

    // remaining prep (independent of x1)
    perm_b_kernel<<<(16*24*4096 + 255)/256, 256>>>(W_dec, Wdec_p, DDIM, IN_DIM, 16, 24, IN_DIM, 0, 1);
    transpose_kernel<<<dim3((OUTD + 31)/32, (HID + 31)/32), dim3(32, 32)>>>(W2, W2T, HID, OUTD);

    // graph pipeline
    row_logits_kernel<<<(NN + 7)/8, dim3(32, 8)>>>(x1, att_src, att_dst, a1s, a1d, NN);
    alpha_kernel<<<(NN + 255)/256, 256>>>(src, dst, a1s, a1d, alpha, NN);
    agg_elu_kernel<<<NN, 128>>>(x1, src, alpha, h1, 0);
    h2px3_kernel<<<(NN + 7)/8, 256, HEAD_SMEM>>>(h1, W2T, W_pred, b_pred, h2, logp, x3);
    agg_elu_kernel<<<NN, 128>>>(x3, src, alpha, h3, 1);
    // h4 = round_tf32(elu(h3 @ W1^T))   [30000,512] K=512  (pipelined path)
    tf32_gemm_kernel<0,3><<<tf32_grid(NN, DDIM), 128, GSMEM_BYTES>>>(
        h3, W1T_p, nullptr, h4, NN, DDIM, HID, 16);
    // out = h4 @ W_dec + b_dec          [30000,3000] K=512 (pipelined path)
    tf32_gemm_kernel<0,0><<<tf32_grid(NN, IN_DIM), 128, GSMEM_BYTES>>>(
        h4, Wdec_p, b_dec, outm, NN, IN_DIM, DDIM, 16);
}

// round 14
// speedup vs baseline: 1.0362x; 1.0014x over previous
#include <cuda_runtime.h>
#include <cuda_bf16.h>
#include <math.h>
#include <stdint.h>

// ---------------- problem constants ----------------
#define NN      30000
#define IN_DIM  3000
#define DDIM    512
#define HID     512
#define OUTD    30
#define PREDD   20
#define DEG     10
#define EDGES   (NN*DEG)
#define NEG_SLOPE 0.2f

// ---------------- scratch ----------------
__device__ float g_x1 [NN*HID];
__device__ float g_h1 [NN*HID];
__device__ float g_x3 [NN*HID];
__device__ float g_h3 [NN*HID];
__device__ float g_h4 [NN*DDIM];
__device__ float g_a1s[NN];
__device__ float g_a1d[NN];
__device__ float g_W2T[OUTD*HID];            // [30][512]
__device__ float g_bfused[HID];              // b_enc @ W1
__device__ float g_Wfused_r[IN_DIM*HID];     // round_tf32(W_enc @ W1), row-major
// fragment-permuted padded B operands: [NB][KB][4096]
__device__ float g_W1_p    [16*4 *4096];     // W1      K=512  N=512
__device__ float g_W1T_p   [16*4 *4096];     // W1^T    K=512  N=512
__device__ float g_Wdec_p  [16*24*4096];     // W_dec   K=512  N=3000(->3072)
__device__ float g_Wfused_p[94*4 *4096];     // Wfused  K=3000(->3008) N=512

// ---------------- tf32 rounding helpers ----------------
__device__ __forceinline__ float round_tf32f(float x) {
    uint32_t u;
    asm("cvt.rna.tf32.f32 %0, %1;" : "=r"(u) : "f"(x));
    return __uint_as_float(u);
}
__device__ __forceinline__ uint32_t f2tf32(float f) {
    uint32_t u;
    asm("cvt.rna.tf32.f32 %0, %1;" : "=r"(u) : "f"(f));
    return u;
}

// =====================================================================
// TF32 tensor-core GEMM (as R13): CTA 128x128, BK=32, 4 warps 64x64,
// 3-stage cp.async.cg, 1 sync/kt; B pre-permuted fragment order.
// =====================================================================
#define GA_STRIDE 36
#define BSTAGE 4096
#define STAGES 3
#define STAGE_FLOATS (128*GA_STRIDE + BSTAGE)
#define GSMEM_BYTES  (STAGES*STAGE_FLOATS*4)

__device__ __forceinline__ void cp16cg(uint32_t dst, const float* src, int sz) {
    asm volatile("cp.async.cg.shared.global [%0], [%1], 16, %2;\n"
                 :: "r"(dst), "l"(src), "r"(sz));
}

template<int ACVT, int FLAGS>
__global__ __launch_bounds__(128, 2) void tf32_gemm_kernel(
    const float* __restrict__ A, const float* __restrict__ Bp,
    const float* __restrict__ bias, float* __restrict__ C,
    int M, int N, int K, int KB)
{
    extern __shared__ float sm[];
    float* As = sm;
    float* Bs = sm + STAGES * 128 * GA_STRIDE;

    const int tid  = threadIdx.x;
    const int lane = tid & 31;
    const int warp = tid >> 5;
    const int wm   = warp >> 1;
    const int wn   = warp & 1;
    const int row0 = blockIdx.y * 128;
    const int col0 = blockIdx.x * 128;
    const int lr   = lane >> 2;
    const int lc   = lane & 3;

    float acc[4][8][4];
    #pragma unroll
    for (int i = 0; i < 4; i++)
        #pragma unroll
        for (int j = 0; j < 8; j++)
            #pragma unroll
            for (int q = 0; q < 4; q++) acc[i][j][q] = 0.f;

    const int nk = KB;
    const float* Btiles = Bp + (size_t)blockIdx.x * KB * BSTAGE;

    auto load_tile = [&](int stage, int kt) {
        const int k0 = kt << 5;
        float* Asb = As + stage * 128 * GA_STRIDE;
        float* Bsb = Bs + stage * BSTAGE;
        #pragma unroll
        for (int it = 0; it < 8; it++) {
            int idx = tid + it * 128;
            int r = idx >> 3, c4 = (idx & 7) << 2;
            int gr = row0 + r, gc = k0 + c4;
            uint32_t dst = (uint32_t)__cvta_generic_to_shared(&Asb[r * GA_STRIDE + c4]);
            int sz = (gr < M && gc < K) ? 16 : 0;
            cp16cg(dst, A + (size_t)gr * K + gc, sz);
        }
        const float* Bt = Btiles + (size_t)kt * BSTAGE;
        #pragma unroll
        for (int it = 0; it < 8; it++) {
            int c4 = (tid + it * 128) << 2;
            uint32_t dst = (uint32_t)__cvta_generic_to_shared(&Bsb[c4]);
            cp16cg(dst, Bt + c4, 16);
        }
    };

    load_tile(0, 0);
    asm volatile("cp.async.commit_group;\n");
    if (nk > 1) load_tile(1, 1);
    asm volatile("cp.async.commit_group;\n");

    int stage = 0;
    for (int kt = 0; kt < nk; kt++) {
        asm volatile("cp.async.wait_group 1;\n");
        __syncthreads();

        if (kt + 2 < nk) load_tile((stage + 2 >= STAGES) ? stage + 2 - STAGES : stage + 2, kt + 2);
        asm volatile("cp.async.commit_group;\n");

        const float*    Asf = As + stage * 128 * GA_STRIDE;
        const uint32_t* Asb = (const uint32_t*)Asf;
        const float*    Bsb = Bs + stage * BSTAGE;

        if (ACVT) {
            #pragma unroll
            for (int ks = 0; ks < 4; ks++) {
                const int kk = ks << 3;
                uint32_t a[4][4];
                uint2 b[8];
                #pragma unroll
                for (int ti = 0; ti < 4; ti++) {
                    int rb = wm * 64 + ti * 16 + lr;
                    int kc = kk + lc;
                    a[ti][0] = f2tf32(Asf[rb * GA_STRIDE + kc]);
                    a[ti][1] = f2tf32(Asf[(rb + 8) * GA_STRIDE + kc]);
                    a[ti][2] = f2tf32(Asf[rb * GA_STRIDE + kc + 4]);
                    a[ti][3] = f2tf32(Asf[(rb + 8) * GA_STRIDE + kc + 4]);
                }
                #pragma unroll
                for (int tj = 0; tj < 8; tj++) {
                    int tjj = wn * 8 + tj;
                    b[tj] = *(const uint2*)(Bsb + (ks << 10) + (tjj << 6) + (lane << 1));
                }
                #pragma unroll
                for (int ti = 0; ti < 4; ti++)
                    #pragma unroll
                    for (int tj = 0; tj < 8; tj++) {
                        asm volatile(
                            "mma.sync.aligned.m16n8k8.row.col.f32.tf32.tf32.f32 "
                            "{%0,%1,%2,%3}, {%4,%5,%6,%7}, {%8,%9}, {%0,%1,%2,%3};\n"
                            : "+f"(acc[ti][tj][0]), "+f"(acc[ti][tj][1]),
                              "+f"(acc[ti][tj][2]), "+f"(acc[ti][tj][3])
                            : "r"(a[ti][0]), "r"(a[ti][1]), "r"(a[ti][2]), "r"(a[ti][3]),
                              "r"(b[tj].x), "r"(b[tj].y));
                    }
            }
        } else {
            uint32_t af[2][4][4];
            uint2    bf[2][8];
            #pragma unroll
            for (int ti = 0; ti < 4; ti++) {
                int rb = wm * 64 + ti * 16 + lr;
                af[0][ti][0] = Asb[rb * GA_STRIDE + lc];
                af[0][ti][1] = Asb[(rb + 8) * GA_STRIDE + lc];
                af[0][ti][2] = Asb[rb * GA_STRIDE + lc + 4];
                af[0][ti][3] = Asb[(rb + 8) * GA_STRIDE + lc + 4];
            }
            #pragma unroll
            for (int tj = 0; tj < 8; tj++) {
                int tjj = wn * 8 + tj;
                bf[0][tj] = *(const uint2*)(Bsb + (tjj << 6) + (lane << 1));
            }
            #pragma unroll
            for (int ks = 0; ks < 4; ks++) {
                const int cur = ks & 1, nxt = cur ^ 1;
                if (ks < 3) {
                    const int kk = (ks + 1) << 3;
                    #pragma unroll
                    for (int ti = 0; ti < 4; ti++) {
                        int rb = wm * 64 + ti * 16 + lr;
                        int kc = kk + lc;
                        af[nxt][ti][0] = Asb[rb * GA_STRIDE + kc];
                        af[nxt][ti][1] = Asb[(rb + 8) * GA_STRIDE + kc];
                        af[nxt][ti][2] = Asb[rb * GA_STRIDE + kc + 4];
                        af[nxt][ti][3] = Asb[(rb + 8) * GA_STRIDE + kc + 4];
                    }
                    #pragma unroll
                    for (int tj = 0; tj < 8; tj++) {
                        int tjj = wn * 8 + tj;
                        bf[nxt][tj] = *(const uint2*)(Bsb + ((ks + 1) << 10) + (tjj << 6) + (lane << 1));
                    }
                }
                #pragma unroll
                for (int ti = 0; ti < 4; ti++)
                    #pragma unroll
                    for (int tj = 0; tj < 8; tj++) {
                        asm volatile(
                            "mma.sync.aligned.m16n8k8.row.col.f32.tf32.tf32.f32 "
                            "{%0,%1,%2,%3}, {%4,%5,%6,%7}, {%8,%9}, {%0,%1,%2,%3};\n"
                            : "+f"(acc[ti][tj][0]), "+f"(acc[ti][tj][1]),
                              "+f"(acc[ti][tj][2]), "+f"(acc[ti][tj][3])
                            : "r"(af[cur][ti][0]), "r"(af[cur][ti][1]),
                              "r"(af[cur][ti][2]), "r"(af[cur][ti][3]),
                              "r"(bf[cur][tj].x), "r"(bf[cur][tj].y));
                    }
            }
        }
        stage = (stage + 1 >= STAGES) ? 0 : stage + 1;
    }

    constexpr bool DO_ELU   = (FLAGS & 1) != 0;
    constexpr bool DO_ROUND = (FLAGS & 2) != 0;
    #pragma unroll
    for (int ti = 0; ti < 4; ti++) {
        int r0 = row0 + wm * 64 + ti * 16 + lr;
        int r1 = r0 + 8;
        #pragma unroll
        for (int tj = 0; tj < 8; tj++) {
            int c = col0 + wn * 64 + tj * 8 + (lc << 1);
            float bv0 = 0.f, bv1 = 0.f;
            if (bias && c + 1 < N) {
                float2 bv = *(const float2*)(bias + c);
                bv0 = bv.x; bv1 = bv.y;
            } else if (bias && c < N) bv0 = bias[c];
            #pragma unroll
            for (int h = 0; h < 2; h++) {
                int r = h ? r1 : r0;
                if (r >= M) continue;
                float v0 = acc[ti][tj][h*2+0] + bv0;
                float v1 = acc[ti][tj][h*2+1] + bv1;
                if (DO_ELU) {
                    v0 = (v0 > 0.f) ? v0 : expm1f(v0);
                    v1 = (v1 > 0.f) ? v1 : expm1f(v1);
                }
                if (DO_ROUND) { v0 = round_tf32f(v0); v1 = round_tf32f(v1); }
                if (c + 1 < N) {
                    float2 st; st.x = v0; st.y = v1;
                    *(float2*)(C + (size_t)r * N + c) = st;
                } else if (c < N) {
                    C[(size_t)r * N + c] = v0;
                }
            }
        }
    }
}

// ---------------- B permutation prep (SOURCE-coalesced) ----------------
// thread i <-> (k, n) with n fastest: reads coalesced; write offset computed.
// dst[nb][kt][ks*1024 + tjj*64 + lane*2 + part], where
// k = kt*32 + ks*8 + part*4 + lc, n = nb*128 + tjj*8 + lr, lane = lr*4+lc.
__global__ void perm_b_kernel(const float* __restrict__ src, float* __restrict__ dst,
                              int K, int N, int KB, int NB, int ld,
                              int trans, int do_round)
{
    int Kp = KB * 32, Np = NB * 128;
    long long i = (long long)blockIdx.x * 256 + threadIdx.x;
    if (i >= (long long)Kp * Np) return;
    int k = (int)(i / Np);
    int n = (int)(i % Np);
    float v = 0.f;
    if (k < K && n < N)
        v = trans ? src[(size_t)n * ld + k] : src[(size_t)k * ld + n];
    if (do_round) v = round_tf32f(v);
    int kt = k >> 5, kr = k & 31;
    int ks = kr >> 3, kq = kr & 7;
    int part = kq >> 2, lc = kq & 3;
    int nb = n >> 7, nr = n & 127;
    int tjj = nr >> 3, lr = nr & 7;
    int lane = lr * 4 + lc;
    size_t off = ((size_t)nb * KB + kt) * 4096 + (ks << 10) + (tjj << 6) + (lane << 1) + part;
    dst[off] = v;
}

// ---------------- other prep ----------------
__global__ void transpose_kernel(const float* __restrict__ in,
                                 float* __restrict__ out, int R, int C)
{
    __shared__ float t[32][33];
    int c = blockIdx.x * 32 + threadIdx.x;
    int r = blockIdx.y * 32 + threadIdx.y;
    if (r < R && c < C) t[threadIdx.y][threadIdx.x] = in[r * C + c];
    __syncthreads();
    int r2 = blockIdx.x * 32 + threadIdx.y;
    int c2 = blockIdx.y * 32 + threadIdx.x;
    if (r2 < C && c2 < R) out[r2 * R + c2] = t[threadIdx.x][threadIdx.y];
}

__global__ void bias_fuse_kernel(const float* __restrict__ b_enc,
                                 const float* __restrict__ W1,
                                 float* __restrict__ bfused)
{
    int n = blockIdx.x * 128 + threadIdx.x;
    if (n >= HID) return;
    float s = 0.f;
    for (int k = 0; k < DDIM; k++) s += b_enc[k] * W1[(size_t)k * HID + n];
    bfused[n] = s;
}

// =====================================================================
// Fused head: h2 = h1@W2, logp = log_softmax(h2@Wp + bp), x3 = h2@W2^T.
// =====================================================================
#define HEAD_SMEM ((OUTD*HID + OUTD*PREDD + PREDD)*4)
__global__ __launch_bounds__(256) void h2px3_kernel(
    const float* __restrict__ h1, const float* __restrict__ W2T,
    const float* __restrict__ Wp, const float* __restrict__ bp,
    float* __restrict__ h2, float* __restrict__ logp, float* __restrict__ x3)
{
    extern __shared__ float sw[];
    float* w   = sw;
    float* wp  = sw + OUTD * HID;
    float* bps = wp + OUTD * PREDD;
    const int tid = threadIdx.x;
    for (int i = tid; i < OUTD * HID; i += 256) w[i] = W2T[i];
    for (int i = tid; i < OUTD * PREDD; i += 256) wp[i] = Wp[i];
    if (tid < PREDD) bps[tid] = bp[tid];
    __syncthreads();

    const int wid = tid >> 5, lane = tid & 31;
    const int row = blockIdx.x * 8 + wid;
    if (row >= NN) return;

    float h[16];
    const float* hr = h1 + (size_t)row * HID;
    #pragma unroll
    for (int j = 0; j < 16; j++) h[j] = hr[lane + 32 * j];

    float xacc[16];
    #pragma unroll
    for (int j = 0; j < 16; j++) xacc[j] = 0.f;
    float p[PREDD];
    #pragma unroll
    for (int c2 = 0; c2 < PREDD; c2++) p[c2] = bps[c2];

    #pragma unroll
    for (int c = 0; c < OUTD; c++) {
        const float* wc = w + c * HID;
        float wv[16];
        #pragma unroll
        for (int j = 0; j < 16; j++) wv[j] = wc[lane + 32 * j];
        float s = 0.f;
        #pragma unroll
        for (int j = 0; j < 16; j++) s += h[j] * wv[j];
        #pragma unroll
        for (int o = 16; o > 0; o >>= 1) s += __shfl_xor_sync(0xffffffffu, s, o);
        if (lane == c) h2[(size_t)row * OUTD + c] = s;
        #pragma unroll
        for (int j = 0; j < 16; j++) xacc[j] += s * wv[j];
        #pragma unroll
        for (int c2 = 0; c2 < PREDD; c2++) p[c2] += s * wp[c * PREDD + c2];
    }

    float* xr = x3 + (size_t)row * HID;
    #pragma unroll
    for (int j = 0; j < 16; j++) xr[lane + 32 * j] = xacc[j];

    float m = -1e30f;
    #pragma unroll
    for (int c2 = 0; c2 < PREDD; c2++) m = fmaxf(m, p[c2]);
    float sum = 0.f;
    #pragma unroll
    for (int c2 = 0; c2 < PREDD; c2++) sum += expf(p[c2] - m);
    float lse = m + logf(sum);
    #pragma unroll
    for (int c2 = 0; c2 < PREDD; c2++)
        if (lane == c2) logp[(size_t)row * PREDD + c2] = p[c2] - lse;
}

// ---------------- attention logits ----------------
__global__ void row_logits_kernel(const float* __restrict__ x1,
                                  const float* __restrict__ att_s,
                                  const float* __restrict__ att_d,
                                  float* __restrict__ a1s,
                                  float* __restrict__ a1d, int n)
{
    int row = blockIdx.x * 8 + threadIdx.y;
    if (row >= n) return;
    int lane = threadIdx.x;
    float s = 0.f, d = 0.f;
    const float* xr = x1 + (size_t)row * HID;
    #pragma unroll 4
    for (int k = lane; k < HID; k += 32) {
        float v = xr[k];
        s += v * att_s[k];
        d += v * att_d[k];
    }
    #pragma unroll
    for (int o = 16; o > 0; o >>= 1) {
        s += __shfl_down_sync(0xffffffffu, s, o);
        d += __shfl_down_sync(0xffffffffu, d, o);
    }
    if (lane == 0) { a1s[row] = s; a1d[row] = d; }
}

// ---------------- aggregation with inline edge softmax + ELU -----------
// Per node i (block): alpha_j = softmax_j(leaky_relu(a1s[src_ij] + a1d[i])),
// out[i] = elu(sum_j alpha_j * x[src_ij]); optional tf32 round.
// Identical math/order to the previous alpha_kernel + agg_elu_kernel.
__global__ __launch_bounds__(128) void agg_elu_kernel(
    const float* __restrict__ x, const int* __restrict__ src,
    const float* __restrict__ a1s, const float* __restrict__ a1d,
    float* __restrict__ out, int round_out)
{
    int i = blockIdx.x;
    __shared__ int   ss[DEG];
    __shared__ float se[DEG];
    __shared__ float sa[DEG];
    if (threadIdx.x < DEG) {
        int sj = src[i * DEG + threadIdx.x];
        ss[threadIdx.x] = sj;
        float v = a1s[sj] + a1d[i];
        se[threadIdx.x] = (v > 0.f) ? v : NEG_SLOPE * v;
    }
    __syncthreads();
    if (threadIdx.x == 0) {
        float m = -1e30f;
        #pragma unroll
        for (int j = 0; j < DEG; j++) m = fmaxf(m, se[j]);
        float e[DEG], sum = 0.f;
        #pragma unroll
        for (int j = 0; j < DEG; j++) { e[j] = __expf(se[j] - m); sum += e[j]; }
        float inv = 1.f / sum;
        #pragma unroll
        for (int j = 0; j < DEG; j++) sa[j] = e[j] * inv;
    }
    __syncthreads();
    int c0 = threadIdx.x * 4;
    float a0 = 0.f, a1 = 0.f, a2 = 0.f, a3 = 0.f;
    #pragma unroll
    for (int j = 0; j < DEG; j++) {
        const float4 v = *(const float4*)&x[(size_t)ss[j] * HID + c0];
        float a = sa[j];
        a0 += a * v.x; a1 += a * v.y; a2 += a * v.z; a3 += a * v.w;
    }
    float4 r;
    r.x = (a0 > 0.f) ? a0 : expm1f(a0);
    r.y = (a1 > 0.f) ? a1 : expm1f(a1);
    r.z = (a2 > 0.f) ? a2 : expm1f(a2);
    r.w = (a3 > 0.f) ? a3 : expm1f(a3);
    if (round_out) {
        r.x = round_tf32f(r.x); r.y = round_tf32f(r.y);
        r.z = round_tf32f(r.z); r.w = round_tf32f(r.w);
    }
    *(float4*)&out[(size_t)i * HID + c0] = r;
}

// ---------------- launch ----------------
static inline dim3 tf32_grid(int M, int N) {
    return dim3((N + 127) / 128, (M + 127) / 128);
}

extern "C" void kernel_launch(void* const* d_in, const int* in_sizes, int n_in,
                              void* d_out, int out_size)
{
    const float* features = (const float*)d_in[0];
    const int*   edge     = (const int*)  d_in[1];
    const float* W_enc    = (const float*)d_in[2];
    const float* b_enc    = (const float*)d_in[3];
    const float* W1       = (const float*)d_in[4];
    const float* att_src  = (const float*)d_in[5];
    const float* att_dst  = (const float*)d_in[6];
    const float* W2       = (const float*)d_in[7];
    const float* W_pred   = (const float*)d_in[8];
    const float* b_pred   = (const float*)d_in[9];
    const float* W_dec    = (const float*)d_in[10];
    const float* b_dec    = (const float*)d_in[11];

    const int* src = edge;

    float* out  = (float*)d_out;
    float* h2   = out;
    float* outm = out + (size_t)NN * OUTD;
    float* logp = out + (size_t)NN * OUTD + (size_t)NN * IN_DIM;

    float *x1, *h1, *x3, *h3, *h4, *a1s, *a1d, *W2T;
    float *bfused, *Wfused_r, *W1_p, *W1T_p, *Wdec_p, *Wfused_p;
    cudaGetSymbolAddress((void**)&x1,    g_x1);
    cudaGetSymbolAddress((void**)&h1,    g_h1);
    cudaGetSymbolAddress((void**)&x3,    g_x3);
    cudaGetSymbolAddress((void**)&h3,    g_h3);
    cudaGetSymbolAddress((void**)&h4,    g_h4);
    cudaGetSymbolAddress((void**)&a1s,   g_a1s);
    cudaGetSymbolAddress((void**)&a1d,   g_a1d);
    cudaGetSymbolAddress((void**)&W2T,   g_W2T);
    cudaGetSymbolAddress((void**)&bfused,   g_bfused);
    cudaGetSymbolAddress((void**)&Wfused_r, g_Wfused_r);
    cudaGetSymbolAddress((void**)&W1_p,     g_W1_p);
    cudaGetSymbolAddress((void**)&W1T_p,    g_W1T_p);
    cudaGetSymbolAddress((void**)&Wdec_p,   g_Wdec_p);
    cudaGetSymbolAddress((void**)&Wfused_p, g_Wfused_p);

    static int attr_set = 0;
    if (!attr_set) {
        cudaFuncSetAttribute(tf32_gemm_kernel<1,2>,
            cudaFuncAttributeMaxDynamicSharedMemorySize, GSMEM_BYTES);
        cudaFuncSetAttribute(tf32_gemm_kernel<1,0>,
            cudaFuncAttributeMaxDynamicSharedMemorySize, GSMEM_BYTES);
        cudaFuncSetAttribute(tf32_gemm_kernel<0,0>,
            cudaFuncAttributeMaxDynamicSharedMemorySize, GSMEM_BYTES);
        cudaFuncSetAttribute(tf32_gemm_kernel<0,3>,
            cudaFuncAttributeMaxDynamicSharedMemorySize, GSMEM_BYTES);
        cudaFuncSetAttribute(h2px3_kernel,
            cudaFuncAttributeMaxDynamicSharedMemorySize, HEAD_SMEM);
        attr_set = 1;
    }

    // ---- weight prep (source-coalesced perms) ----
    perm_b_kernel<<<(512*512 + 255)/256, 256>>>(W1, W1_p, DDIM, HID, 16, 4, HID, 0, 1);
    perm_b_kernel<<<(512*512 + 255)/256, 256>>>(W1, W1T_p, HID, DDIM, 16, 4, HID, 1, 1);
    bias_fuse_kernel<<<(HID + 127)/128, 128>>>(b_enc, W1, bfused);
    tf32_gemm_kernel<1,2><<<tf32_grid(IN_DIM, HID), 128, GSMEM_BYTES>>>(
        W_enc, W1_p, nullptr, Wfused_r, IN_DIM, HID, DDIM, 16);
    perm_b_kernel<<<(3008*512 + 255)/256, 256>>>(Wfused_r, Wfused_p, IN_DIM, HID, 94, 4, HID, 0, 0);
    // 6: x1 = features @ Wfused + bfused   [30000,512] K=3000
    tf32_gemm_kernel<1,0><<<tf32_grid(NN, HID), 128, GSMEM_BYTES>>>(
        features, Wfused_p, bfused, x1, NN, HID, IN_DIM, 94);

    // remaining prep (independent of x1)
    perm_b_kernel<<<(512*3072 + 255)/256, 256>>>(W_dec, Wdec_p, DDIM, IN_DIM, 16, 24, IN_DIM, 0, 1);
    transpose_kernel<<<dim3((OUTD + 31)/32, (HID + 31)/32), dim3(32, 32)>>>(W2, W2T, HID, OUTD);

    // graph pipeline
    row_logits_kernel<<<(NN + 7)/8, dim3(32, 8)>>>(x1, att_src, att_dst, a1s, a1d, NN);
    agg_elu_kernel<<<NN, 128>>>(x1, src, a1s, a1d, h1, 0);
    h2px3_kernel<<<(NN + 7)/8, 256, HEAD_SMEM>>>(h1, W2T, W_pred, b_pred, h2, logp, x3);
    agg_elu_kernel<<<NN, 128>>>(x3, src, a1s, a1d, h3, 1);
    // h4 = round_tf32(elu(h3 @ W1^T))   [30000,512] K=512
    tf32_gemm_kernel<0,3><<<tf32_grid(NN, DDIM), 128, GSMEM_BYTES>>>(
        h3, W1T_p, nullptr, h4, NN, DDIM, HID, 16);
    // out = h4 @ W_dec + b_dec          [30000,3000] K=512
    tf32_gemm_kernel<0,0><<<tf32_grid(NN, IN_DIM), 128, GSMEM_BYTES>>>(
        h4, Wdec_p, b_dec, outm, NN, IN_DIM, DDIM, 16);
}

// round 15
// speedup vs baseline: 1.4667x; 1.4156x over previous
#include <cuda_runtime.h>
#include <cuda_fp16.h>
#include <math.h>
#include <stdint.h>

// ---------------- problem constants ----------------
#define NN      30000
#define IN_DIM  3000
#define DDIM    512
#define HID     512
#define OUTD    30
#define PREDD   20
#define DEG     10
#define EDGES   (NN*DEG)
#define NEG_SLOPE 0.2f

// ---------------- scratch ----------------
__device__ float  g_x1 [NN*HID];
__device__ float  g_h1 [NN*HID];
__device__ float  g_x3 [NN*HID];
__device__ float  g_a1s[NN];
__device__ float  g_a1d[NN];
__device__ float  g_W2T[OUTD*HID];
__device__ float  g_bfused[HID];
__device__ float  g_Wfused_r[IN_DIM*HID];      // fp32 Wfused (perm input)
__device__ __half g_feat_h[(size_t)NN*IN_DIM]; // fp16 features
__device__ __half g_Wenc_h[IN_DIM*DDIM];       // fp16 W_enc (A of prep GEMM)
__device__ __half g_h3_h [NN*HID];             // fp16 h3
__device__ __half g_h4_h [NN*DDIM];            // fp16 elu(h4)
// fragment-permuted fp16 B tiles: [NB][KB][4096 halves]  (tile = 32K x 128N)
__device__ __half g_W1_ph    [16*4 *4096];
__device__ __half g_W1T_ph   [16*4 *4096];
__device__ __half g_Wdec_ph  [16*24*4096];
__device__ __half g_Wfused_ph[94*4 *4096];

// =====================================================================
// FP16 tensor-core GEMM: C[M,N] = A[M,K](fp16) @ B(perm fp16) (+bias)
// CTA 128x128, BK=32 (2 x k16), 4 warps (2x2), warp tile 64x64.
// mma.sync.m16n8k16.f32.f16.f16.f32; 3-stage cp.async.cg, 1 sync/kt.
// A smem: rows padded to 40 halves (80B) -> all-32-bank LDS.
// B smem: contiguous fragment-order tile (8KB), uint2 loads conflict-free.
// FLAGS bit0 = ELU, bit1 = fp16 output (C16).
// =====================================================================
#define HA_ROWB   80                    // bytes per A smem row
#define A_STAGE_B 10240                 // 128*80
#define B_STAGE_B 8192
#define STAGE_B   (A_STAGE_B + B_STAGE_B)
#define STAGES    3
#define GSMEM_BYTES (STAGES*STAGE_B)    // 55296

__device__ __forceinline__ void cp16cg(uint32_t dst, const void* src, int sz) {
    asm volatile("cp.async.cg.shared.global [%0], [%1], 16, %2;\n"
                 :: "r"(dst), "l"(src), "r"(sz));
}

template<int FLAGS>
__global__ __launch_bounds__(128, 2) void h16_gemm_kernel(
    const __half* __restrict__ A, const __half* __restrict__ Bp,
    const float* __restrict__ bias, float* __restrict__ C,
    __half* __restrict__ C16, int M, int N, int K, int KB)
{
    extern __shared__ char sm[];
    const uint32_t smb = (uint32_t)__cvta_generic_to_shared(sm);

    const int tid  = threadIdx.x;
    const int lane = tid & 31;
    const int warp = tid >> 5;
    const int wm   = warp >> 1;
    const int wn   = warp & 1;
    const int row0 = blockIdx.y * 128;
    const int col0 = blockIdx.x * 128;
    const int lr   = lane >> 2;
    const int lc   = lane & 3;

    float acc[4][8][4];
    #pragma unroll
    for (int i = 0; i < 4; i++)
        #pragma unroll
        for (int j = 0; j < 8; j++)
            #pragma unroll
            for (int q = 0; q < 4; q++) acc[i][j][q] = 0.f;

    const int nk = KB;
    const __half* Btiles = Bp + (size_t)blockIdx.x * KB * 4096;

    auto load_tile = [&](int stage, int kt) {
        const int k0 = kt << 5;
        const uint32_t Asb = smb + stage * STAGE_B;
        const uint32_t Bsb = Asb + A_STAGE_B;
        // A: 128 rows x 32 halves (64B) = 512 x 16B chunks
        #pragma unroll
        for (int it = 0; it < 4; it++) {
            int idx = tid + it * 128;
            int r = idx >> 2, ch = idx & 3;
            int gr = row0 + r, gc = k0 + ch * 8;
            int sz = (gr < M && gc < K) ? 16 : 0;
            cp16cg(Asb + r * HA_ROWB + ch * 16, A + (size_t)gr * K + gc, sz);
        }
        // B: 8192 bytes contiguous
        const __half* Bt = Btiles + (size_t)kt * 4096;
        #pragma unroll
        for (int it = 0; it < 4; it++) {
            int cb = (tid + it * 128) << 4;
            cp16cg(Bsb + cb, (const char*)Bt + cb, 16);
        }
    };

    load_tile(0, 0);
    asm volatile("cp.async.commit_group;\n");
    if (nk > 1) load_tile(1, 1);
    asm volatile("cp.async.commit_group;\n");

    int stage = 0;
    for (int kt = 0; kt < nk; kt++) {
        asm volatile("cp.async.wait_group 1;\n");
        __syncthreads();

        if (kt + 2 < nk) load_tile((stage + 2 >= STAGES) ? stage + 2 - STAGES : stage + 2, kt + 2);
        asm volatile("cp.async.commit_group;\n");

        const uint32_t* Asb = (const uint32_t*)(sm + stage * STAGE_B);
        const char*     Bsb = sm + stage * STAGE_B + A_STAGE_B;

        #pragma unroll
        for (int ks = 0; ks < 2; ks++) {
            uint32_t a[4][4];
            uint2 b[8];
            #pragma unroll
            for (int ti = 0; ti < 4; ti++) {
                int rb = wm * 64 + ti * 16 + lr;
                int base = rb * 20 + ks * 8 + lc;       // uint32 index
                a[ti][0] = Asb[base];
                a[ti][1] = Asb[base + 160];             // row+8
                a[ti][2] = Asb[base + 4];               // k+8
                a[ti][3] = Asb[base + 164];
            }
            #pragma unroll
            for (int tj = 0; tj < 8; tj++) {
                int tjj = wn * 8 + tj;
                b[tj] = *(const uint2*)(Bsb + ks * 4096 + tjj * 256 + lane * 8);
            }
            #pragma unroll
            for (int ti = 0; ti < 4; ti++)
                #pragma unroll
                for (int tj = 0; tj < 8; tj++) {
                    asm volatile(
                        "mma.sync.aligned.m16n8k16.row.col.f32.f16.f16.f32 "
                        "{%0,%1,%2,%3}, {%4,%5,%6,%7}, {%8,%9}, {%0,%1,%2,%3};\n"
                        : "+f"(acc[ti][tj][0]), "+f"(acc[ti][tj][1]),
                          "+f"(acc[ti][tj][2]), "+f"(acc[ti][tj][3])
                        : "r"(a[ti][0]), "r"(a[ti][1]), "r"(a[ti][2]), "r"(a[ti][3]),
                          "r"(b[tj].x), "r"(b[tj].y));
                }
        }
        stage = (stage + 1 >= STAGES) ? 0 : stage + 1;
    }

    constexpr bool DO_ELU = (FLAGS & 1) != 0;
    constexpr bool DO_H16 = (FLAGS & 2) != 0;
    #pragma unroll
    for (int ti = 0; ti < 4; ti++) {
        int r0 = row0 + wm * 64 + ti * 16 + lr;
        int r1 = r0 + 8;
        #pragma unroll
        for (int tj = 0; tj < 8; tj++) {
            int c = col0 + wn * 64 + tj * 8 + (lc << 1);
            float bv0 = 0.f, bv1 = 0.f;
            if (bias && c + 1 < N) {
                float2 bv = *(const float2*)(bias + c);
                bv0 = bv.x; bv1 = bv.y;
            } else if (bias && c < N) bv0 = bias[c];
            #pragma unroll
            for (int h = 0; h < 2; h++) {
                int r = h ? r1 : r0;
                if (r >= M) continue;
                float v0 = acc[ti][tj][h*2+0] + bv0;
                float v1 = acc[ti][tj][h*2+1] + bv1;
                if (DO_ELU) {
                    v0 = (v0 > 0.f) ? v0 : expm1f(v0);
                    v1 = (v1 > 0.f) ? v1 : expm1f(v1);
                }
                if (DO_H16) {
                    if (c + 1 < N)
                        *(__half2*)(C16 + (size_t)r * N + c) = __floats2half2_rn(v0, v1);
                    else if (c < N)
                        C16[(size_t)r * N + c] = __float2half(v0);
                } else {
                    if (c + 1 < N) {
                        float2 st; st.x = v0; st.y = v1;
                        *(float2*)(C + (size_t)r * N + c) = st;
                    } else if (c < N) {
                        C[(size_t)r * N + c] = v0;
                    }
                }
            }
        }
    }
}

// ---------------- fp32 -> fp16 convert (vectorized) ----------------
__global__ void f2h_kernel(const float* __restrict__ in,
                           __half* __restrict__ out, long long n4)
{
    long long i = (long long)blockIdx.x * 256 + threadIdx.x;
    if (i >= n4) return;
    float4 v = *(const float4*)(in + i * 4);
    __half2 h01 = __floats2half2_rn(v.x, v.y);
    __half2 h23 = __floats2half2_rn(v.z, v.w);
    uint2 st;
    st.x = *(uint32_t*)&h01;
    st.y = *(uint32_t*)&h23;
    *(uint2*)(out + i * 4) = st;
}

// ---------------- B permutation to fp16 fragment order ----------------
// k = kt*32 + ks*16 + reg*8 + lc*2 + h ; n = nb*128 + tjj*8 + lr
// off = ((nb*KB+kt)*4096) + ks*2048 + tjj*128 + (lr*4+lc)*4 + reg*2 + h
__global__ void perm_bh_kernel(const float* __restrict__ src, __half* __restrict__ dst,
                               int K, int N, int KB, int NB, int ld, int trans)
{
    int Kp = KB * 32, Np = NB * 128;
    long long i = (long long)blockIdx.x * 256 + threadIdx.x;
    if (i >= (long long)Kp * Np) return;
    int k = (int)(i / Np);
    int n = (int)(i % Np);
    float v = 0.f;
    if (k < K && n < N)
        v = trans ? src[(size_t)n * ld + k] : src[(size_t)k * ld + n];
    int kt = k >> 5, kr = k & 31;
    int ks = kr >> 4, kq = kr & 15;
    int reg = kq >> 3, kb = kq & 7;
    int lc = kb >> 1, h = kb & 1;
    int nb = n >> 7, nr = n & 127;
    int tjj = nr >> 3, lr = nr & 7;
    int lane = lr * 4 + lc;
    size_t off = ((size_t)nb * KB + kt) * 4096 + (ks << 11) + (tjj << 7) + (lane << 2) + (reg << 1) + h;
    dst[off] = __float2half(v);
}

// ---------------- other prep ----------------
__global__ void transpose_kernel(const float* __restrict__ in,
                                 float* __restrict__ out, int R, int C)
{
    __shared__ float t[32][33];
    int c = blockIdx.x * 32 + threadIdx.x;
    int r = blockIdx.y * 32 + threadIdx.y;
    if (r < R && c < C) t[threadIdx.y][threadIdx.x] = in[r * C + c];
    __syncthreads();
    int r2 = blockIdx.x * 32 + threadIdx.y;
    int c2 = blockIdx.y * 32 + threadIdx.x;
    if (r2 < C && c2 < R) out[r2 * R + c2] = t[threadIdx.x][threadIdx.y];
}

__global__ void bias_fuse_kernel(const float* __restrict__ b_enc,
                                 const float* __restrict__ W1,
                                 float* __restrict__ bfused)
{
    int n = blockIdx.x * 128 + threadIdx.x;
    if (n >= HID) return;
    float s = 0.f;
    for (int k = 0; k < DDIM; k++) s += b_enc[k] * W1[(size_t)k * HID + n];
    bfused[n] = s;
}

// ---------------- fused head ----------------
#define HEAD_SMEM ((OUTD*HID + OUTD*PREDD + PREDD)*4)
__global__ __launch_bounds__(256) void h2px3_kernel(
    const float* __restrict__ h1, const float* __restrict__ W2T,
    const float* __restrict__ Wp, const float* __restrict__ bp,
    float* __restrict__ h2, float* __restrict__ logp, float* __restrict__ x3)
{
    extern __shared__ float sw[];
    float* w   = sw;
    float* wp  = sw + OUTD * HID;
    float* bps = wp + OUTD * PREDD;
    const int tid = threadIdx.x;
    for (int i = tid; i < OUTD * HID; i += 256) w[i] = W2T[i];
    for (int i = tid; i < OUTD * PREDD; i += 256) wp[i] = Wp[i];
    if (tid < PREDD) bps[tid] = bp[tid];
    __syncthreads();

    const int wid = tid >> 5, lane = tid & 31;
    const int row = blockIdx.x * 8 + wid;
    if (row >= NN) return;

    float h[16];
    const float* hr = h1 + (size_t)row * HID;
    #pragma unroll
    for (int j = 0; j < 16; j++) h[j] = hr[lane + 32 * j];

    float xacc[16];
    #pragma unroll
    for (int j = 0; j < 16; j++) xacc[j] = 0.f;
    float p[PREDD];
    #pragma unroll
    for (int c2 = 0; c2 < PREDD; c2++) p[c2] = bps[c2];

    #pragma unroll
    for (int c = 0; c < OUTD; c++) {
        const float* wc = w + c * HID;
        float wv[16];
        #pragma unroll
        for (int j = 0; j < 16; j++) wv[j] = wc[lane + 32 * j];
        float s = 0.f;
        #pragma unroll
        for (int j = 0; j < 16; j++) s += h[j] * wv[j];
        #pragma unroll
        for (int o = 16; o > 0; o >>= 1) s += __shfl_xor_sync(0xffffffffu, s, o);
        if (lane == c) h2[(size_t)row * OUTD + c] = s;
        #pragma unroll
        for (int j = 0; j < 16; j++) xacc[j] += s * wv[j];
        #pragma unroll
        for (int c2 = 0; c2 < PREDD; c2++) p[c2] += s * wp[c * PREDD + c2];
    }

    float* xr = x3 + (size_t)row * HID;
    #pragma unroll
    for (int j = 0; j < 16; j++) xr[lane + 32 * j] = xacc[j];

    float m = -1e30f;
    #pragma unroll
    for (int c2 = 0; c2 < PREDD; c2++) m = fmaxf(m, p[c2]);
    float sum = 0.f;
    #pragma unroll
    for (int c2 = 0; c2 < PREDD; c2++) sum += expf(p[c2] - m);
    float lse = m + logf(sum);
    #pragma unroll
    for (int c2 = 0; c2 < PREDD; c2++)
        if (lane == c2) logp[(size_t)row * PREDD + c2] = p[c2] - lse;
}

// ---------------- attention logits ----------------
__global__ void row_logits_kernel(const float* __restrict__ x1,
                                  const float* __restrict__ att_s,
                                  const float* __restrict__ att_d,
                                  float* __restrict__ a1s,
                                  float* __restrict__ a1d, int n)
{
    int row = blockIdx.x * 8 + threadIdx.y;
    if (row >= n) return;
    int lane = threadIdx.x;
    float s = 0.f, d = 0.f;
    const float* xr = x1 + (size_t)row * HID;
    #pragma unroll 4
    for (int k = lane; k < HID; k += 32) {
        float v = xr[k];
        s += v * att_s[k];
        d += v * att_d[k];
    }
    #pragma unroll
    for (int o = 16; o > 0; o >>= 1) {
        s += __shfl_down_sync(0xffffffffu, s, o);
        d += __shfl_down_sync(0xffffffffu, d, o);
    }
    if (lane == 0) { a1s[row] = s; a1d[row] = d; }
}

// ---------------- aggregation with inline softmax + ELU ----------------
// out_f != nullptr -> fp32 out; out_h != nullptr -> fp16 out.
__global__ __launch_bounds__(128) void agg_elu_kernel(
    const float* __restrict__ x, const int* __restrict__ src,
    const float* __restrict__ a1s, const float* __restrict__ a1d,
    float* __restrict__ out_f, __half* __restrict__ out_h)
{
    int i = blockIdx.x;
    __shared__ int   ss[DEG];
    __shared__ float se[DEG];
    __shared__ float sa[DEG];
    if (threadIdx.x < DEG) {
        int sj = src[i * DEG + threadIdx.x];
        ss[threadIdx.x] = sj;
        float v = a1s[sj] + a1d[i];
        se[threadIdx.x] = (v > 0.f) ? v : NEG_SLOPE * v;
    }
    __syncthreads();
    if (threadIdx.x == 0) {
        float m = -1e30f;
        #pragma unroll
        for (int j = 0; j < DEG; j++) m = fmaxf(m, se[j]);
        float e[DEG], sum = 0.f;
        #pragma unroll
        for (int j = 0; j < DEG; j++) { e[j] = __expf(se[j] - m); sum += e[j]; }
        float inv = 1.f / sum;
        #pragma unroll
        for (int j = 0; j < DEG; j++) sa[j] = e[j] * inv;
    }
    __syncthreads();
    int c0 = threadIdx.x * 4;
    float a0 = 0.f, a1 = 0.f, a2 = 0.f, a3 = 0.f;
    #pragma unroll
    for (int j = 0; j < DEG; j++) {
        const float4 v = *(const float4*)&x[(size_t)ss[j] * HID + c0];
        float a = sa[j];
        a0 += a * v.x; a1 += a * v.y; a2 += a * v.z; a3 += a * v.w;
    }
    float4 r;
    r.x = (a0 > 0.f) ? a0 : expm1f(a0);
    r.y = (a1 > 0.f) ? a1 : expm1f(a1);
    r.z = (a2 > 0.f) ? a2 : expm1f(a2);
    r.w = (a3 > 0.f) ? a3 : expm1f(a3);
    if (out_f) *(float4*)&out_f[(size_t)i * HID + c0] = r;
    if (out_h) {
        __half2 h01 = __floats2half2_rn(r.x, r.y);
        __half2 h23 = __floats2half2_rn(r.z, r.w);
        uint2 st;
        st.x = *(uint32_t*)&h01;
        st.y = *(uint32_t*)&h23;
        *(uint2*)&out_h[(size_t)i * HID + c0] = st;
    }
}

// ---------------- launch ----------------
static inline dim3 h16_grid(int M, int NB) {
    return dim3(NB, (M + 127) / 128);
}

extern "C" void kernel_launch(void* const* d_in, const int* in_sizes, int n_in,
                              void* d_out, int out_size)
{
    const float* features = (const float*)d_in[0];
    const int*   edge     = (const int*)  d_in[1];
    const float* W_enc    = (const float*)d_in[2];
    const float* b_enc    = (const float*)d_in[3];
    const float* W1       = (const float*)d_in[4];
    const float* att_src  = (const float*)d_in[5];
    const float* att_dst  = (const float*)d_in[6];
    const float* W2       = (const float*)d_in[7];
    const float* W_pred   = (const float*)d_in[8];
    const float* b_pred   = (const float*)d_in[9];
    const float* W_dec    = (const float*)d_in[10];
    const float* b_dec    = (const float*)d_in[11];

    const int* src = edge;

    float* out  = (float*)d_out;
    float* h2   = out;
    float* outm = out + (size_t)NN * OUTD;
    float* logp = out + (size_t)NN * OUTD + (size_t)NN * IN_DIM;

    float *x1, *h1, *x3, *a1s, *a1d, *W2T, *bfused, *Wfused_r;
    __half *feat_h, *Wenc_h, *h3_h, *h4_h, *W1_ph, *W1T_ph, *Wdec_ph, *Wfused_ph;
    cudaGetSymbolAddress((void**)&x1,    g_x1);
    cudaGetSymbolAddress((void**)&h1,    g_h1);
    cudaGetSymbolAddress((void**)&x3,    g_x3);
    cudaGetSymbolAddress((void**)&a1s,   g_a1s);
    cudaGetSymbolAddress((void**)&a1d,   g_a1d);
    cudaGetSymbolAddress((void**)&W2T,   g_W2T);
    cudaGetSymbolAddress((void**)&bfused,   g_bfused);
    cudaGetSymbolAddress((void**)&Wfused_r, g_Wfused_r);
    cudaGetSymbolAddress((void**)&feat_h,   g_feat_h);
    cudaGetSymbolAddress((void**)&Wenc_h,   g_Wenc_h);
    cudaGetSymbolAddress((void**)&h3_h,     g_h3_h);
    cudaGetSymbolAddress((void**)&h4_h,     g_h4_h);
    cudaGetSymbolAddress((void**)&W1_ph,    g_W1_ph);
    cudaGetSymbolAddress((void**)&W1T_ph,   g_W1T_ph);
    cudaGetSymbolAddress((void**)&Wdec_ph,  g_Wdec_ph);
    cudaGetSymbolAddress((void**)&Wfused_ph, g_Wfused_ph);

    static int attr_set = 0;
    if (!attr_set) {
        cudaFuncSetAttribute(h16_gemm_kernel<0>,
            cudaFuncAttributeMaxDynamicSharedMemorySize, GSMEM_BYTES);
        cudaFuncSetAttribute(h16_gemm_kernel<3>,
            cudaFuncAttributeMaxDynamicSharedMemorySize, GSMEM_BYTES);
        cudaFuncSetAttribute(h2px3_kernel,
            cudaFuncAttributeMaxDynamicSharedMemorySize, HEAD_SMEM);
        attr_set = 1;
    }

    // ---- prep ----
    f2h_kernel<<<(int)(((long long)NN*IN_DIM/4 + 255)/256), 256>>>(features, feat_h, (long long)NN*IN_DIM/4);
    f2h_kernel<<<(IN_DIM*DDIM/4 + 255)/256, 256>>>(W_enc, Wenc_h, IN_DIM*DDIM/4);
    perm_bh_kernel<<<(512*512 + 255)/256, 256>>>(W1, W1_ph, DDIM, HID, 16, 4, HID, 0);
    perm_bh_kernel<<<(512*512 + 255)/256, 256>>>(W1, W1T_ph, HID, DDIM, 16, 4, HID, 1);
    bias_fuse_kernel<<<(HID + 127)/128, 128>>>(b_enc, W1, bfused);
    // Wfused = W_enc @ W1  [3000,512] K=512 (fp32 out)
    h16_gemm_kernel<0><<<h16_grid(IN_DIM, 4), 128, GSMEM_BYTES>>>(
        Wenc_h, W1_ph, nullptr, Wfused_r, nullptr, IN_DIM, HID, DDIM, 16);
    perm_bh_kernel<<<(3008*512 + 255)/256, 256>>>(Wfused_r, Wfused_ph, IN_DIM, HID, 94, 4, HID, 0);
    // x1 = features @ Wfused + bfused   [30000,512] K=3000
    h16_gemm_kernel<0><<<h16_grid(NN, 4), 128, GSMEM_BYTES>>>(
        feat_h, Wfused_ph, bfused, x1, nullptr, NN, HID, IN_DIM, 94);

    perm_bh_kernel<<<(512*3072 + 255)/256, 256>>>(W_dec, Wdec_ph, DDIM, IN_DIM, 16, 24, IN_DIM, 0);
    transpose_kernel<<<dim3((OUTD + 31)/32, (HID + 31)/32), dim3(32, 32)>>>(W2, W2T, HID, OUTD);

    // graph pipeline
    row_logits_kernel<<<(NN + 7)/8, dim3(32, 8)>>>(x1, att_src, att_dst, a1s, a1d, NN);
    agg_elu_kernel<<<NN, 128>>>(x1, src, a1s, a1d, h1, nullptr);
    h2px3_kernel<<<(NN + 7)/8, 256, HEAD_SMEM>>>(h1, W2T, W_pred, b_pred, h2, logp, x3);
    agg_elu_kernel<<<NN, 128>>>(x3, src, a1s, a1d, nullptr, h3_h);
    // h4_h = elu(h3 @ W1^T)  [30000,512] K=512, fp16 out
    h16_gemm_kernel<3><<<h16_grid(NN, 4), 128, GSMEM_BYTES>>>(
        h3_h, W1T_ph, nullptr, nullptr, h4_h, NN, DDIM, HID, 16);
    // out = h4 @ W_dec + b_dec  [30000,3000] K=512
    h16_gemm_kernel<0><<<h16_grid(NN, 24), 128, GSMEM_BYTES>>>(
        h4_h, Wdec_ph, b_dec, outm, nullptr, NN, IN_DIM, DDIM, 16);
}

// round 16
// speedup vs baseline: 1.4863x; 1.0133x over previous
#include <cuda_runtime.h>
#include <cuda_fp16.h>
#include <math.h>
#include <stdint.h>

// ---------------- problem constants ----------------
#define NN      30000
#define IN_DIM  3000
#define DDIM    512
#define HID     512
#define OUTD    30
#define PREDD   20
#define DEG     10
#define EDGES   (NN*DEG)
#define NEG_SLOPE 0.2f

// ---------------- scratch ----------------
__device__ float  g_x1 [NN*HID];
__device__ float  g_h1 [NN*HID];
__device__ float  g_x3 [NN*HID];
__device__ float  g_a1s[NN];
__device__ float  g_a1d[NN];
__device__ float  g_W2T[OUTD*HID];
__device__ float  g_bfused[HID];
__device__ float  g_Wfused_r[IN_DIM*HID];
__device__ __half g_feat_h[(size_t)NN*IN_DIM];
__device__ __half g_Wenc_h[IN_DIM*DDIM];
__device__ __half g_h3_h [NN*HID];
__device__ __half g_h4_h [NN*DDIM];
// fragment-permuted fp16 B tiles: [NB][KB][4096 halves] (tile = 32K x 128N)
__device__ __half g_W1_ph    [16*4 *4096];
__device__ __half g_W1T_ph   [16*4 *4096];
__device__ __half g_Wdec_ph  [16*24*4096];
__device__ __half g_Wfused_ph[94*4 *4096];

// =====================================================================
// FP16 tensor-core GEMM: C[M,N] = A[M,K](fp16) @ B(perm fp16) (+bias)
// CTA 128x128, BK=64 (4 x k16), 4 warps (2x2), warp tile 64x64.
// mma.sync.m16n8k16; 3-stage cp.async.cg, 1 sync per 64-k iteration.
// A smem: rows padded to 72 halves (144B) -> all-32-bank LDS
//   (uint32 bank = (36r + 8ks + lc) mod 32 = 4*lr + lc, all distinct).
// B smem: two contiguous fragment-order 32-k tiles (16KB).
// FLAGS bit0 = ELU, bit1 = fp16 output (C16).
// KB = number of 32-k permuted tiles (even for all instances here).
// =====================================================================
#define HA_ROWB   144
#define A_STAGE_B (128*HA_ROWB)         // 18432
#define B_STAGE_B 16384
#define STAGE_B   (A_STAGE_B + B_STAGE_B)
#define STAGES    3
#define GSMEM_BYTES (STAGES*STAGE_B)    // 104448

__device__ __forceinline__ void cp16cg(uint32_t dst, const void* src, int sz) {
    asm volatile("cp.async.cg.shared.global [%0], [%1], 16, %2;\n"
                 :: "r"(dst), "l"(src), "r"(sz));
}

template<int FLAGS>
__global__ __launch_bounds__(128, 2) void h16_gemm_kernel(
    const __half* __restrict__ A, const __half* __restrict__ Bp,
    const float* __restrict__ bias, float* __restrict__ C,
    __half* __restrict__ C16, int M, int N, int K, int KB)
{
    extern __shared__ char sm[];
    const uint32_t smb = (uint32_t)__cvta_generic_to_shared(sm);

    const int tid  = threadIdx.x;
    const int lane = tid & 31;
    const int warp = tid >> 5;
    const int wm   = warp >> 1;
    const int wn   = warp & 1;
    const int row0 = blockIdx.y * 128;
    const int col0 = blockIdx.x * 128;
    const int lr   = lane >> 2;
    const int lc   = lane & 3;

    float acc[4][8][4];
    #pragma unroll
    for (int i = 0; i < 4; i++)
        #pragma unroll
        for (int j = 0; j < 8; j++)
            #pragma unroll
            for (int q = 0; q < 4; q++) acc[i][j][q] = 0.f;

    const int nk2 = KB >> 1;                      // 64-k iterations
    const __half* Btiles = Bp + (size_t)blockIdx.x * KB * 4096;

    auto load_tile = [&](int stage, int t) {
        const int k0 = t << 6;
        const uint32_t Asb = smb + stage * STAGE_B;
        const uint32_t Bsb = Asb + A_STAGE_B;
        // A: 128 rows x 64 halves (128B) = 1024 x 16B chunks, 8/thread
        #pragma unroll
        for (int it = 0; it < 8; it++) {
            int idx = tid + it * 128;
            int r = idx >> 3, ch = idx & 7;
            int gr = row0 + r, gc = k0 + ch * 8;
            int sz = (gr < M && gc < K) ? 16 : 0;
            cp16cg(Asb + r * HA_ROWB + ch * 16, A + (size_t)gr * K + gc, sz);
        }
        // B: 16384 bytes contiguous (two 32-k fragment tiles)
        const __half* Bt = Btiles + (size_t)t * 8192;
        #pragma unroll
        for (int it = 0; it < 8; it++) {
            int cb = (tid + it * 128) << 4;
            cp16cg(Bsb + cb, (const char*)Bt + cb, 16);
        }
    };

    load_tile(0, 0);
    asm volatile("cp.async.commit_group;\n");
    if (nk2 > 1) load_tile(1, 1);
    asm volatile("cp.async.commit_group;\n");

    int stage = 0;
    for (int t = 0; t < nk2; t++) {
        asm volatile("cp.async.wait_group 1;\n");
        __syncthreads();

        if (t + 2 < nk2) load_tile((stage + 2 >= STAGES) ? stage + 2 - STAGES : stage + 2, t + 2);
        asm volatile("cp.async.commit_group;\n");

        const uint32_t* Asb = (const uint32_t*)(sm + stage * STAGE_B);
        const char*     Bsb = sm + stage * STAGE_B + A_STAGE_B;

        #pragma unroll
        for (int ks = 0; ks < 4; ks++) {          // 4 x k16
            uint32_t a[4][4];
            uint2 b[8];
            #pragma unroll
            for (int ti = 0; ti < 4; ti++) {
                int rb = wm * 64 + ti * 16 + lr;
                int base = rb * 36 + ks * 8 + lc;
                a[ti][0] = Asb[base];
                a[ti][1] = Asb[base + 288];        // row+8 (8*36)
                a[ti][2] = Asb[base + 4];          // k+8
                a[ti][3] = Asb[base + 292];
            }
            #pragma unroll
            for (int tj = 0; tj < 8; tj++) {
                int tjj = wn * 8 + tj;
                b[tj] = *(const uint2*)(Bsb + ks * 4096 + tjj * 256 + lane * 8);
            }
            #pragma unroll
            for (int ti = 0; ti < 4; ti++)
                #pragma unroll
                for (int tj = 0; tj < 8; tj++) {
                    asm volatile(
                        "mma.sync.aligned.m16n8k16.row.col.f32.f16.f16.f32 "
                        "{%0,%1,%2,%3}, {%4,%5,%6,%7}, {%8,%9}, {%0,%1,%2,%3};\n"
                        : "+f"(acc[ti][tj][0]), "+f"(acc[ti][tj][1]),
                          "+f"(acc[ti][tj][2]), "+f"(acc[ti][tj][3])
                        : "r"(a[ti][0]), "r"(a[ti][1]), "r"(a[ti][2]), "r"(a[ti][3]),
                          "r"(b[tj].x), "r"(b[tj].y));
                }
        }
        stage = (stage + 1 >= STAGES) ? 0 : stage + 1;
    }

    constexpr bool DO_ELU = (FLAGS & 1) != 0;
    constexpr bool DO_H16 = (FLAGS & 2) != 0;
    #pragma unroll
    for (int ti = 0; ti < 4; ti++) {
        int r0 = row0 + wm * 64 + ti * 16 + lr;
        int r1 = r0 + 8;
        #pragma unroll
        for (int tj = 0; tj < 8; tj++) {
            int c = col0 + wn * 64 + tj * 8 + (lc << 1);
            float bv0 = 0.f, bv1 = 0.f;
            if (bias && c + 1 < N) {
                float2 bv = *(const float2*)(bias + c);
                bv0 = bv.x; bv1 = bv.y;
            } else if (bias && c < N) bv0 = bias[c];
            #pragma unroll
            for (int h = 0; h < 2; h++) {
                int r = h ? r1 : r0;
                if (r >= M) continue;
                float v0 = acc[ti][tj][h*2+0] + bv0;
                float v1 = acc[ti][tj][h*2+1] + bv1;
                if (DO_ELU) {
                    v0 = (v0 > 0.f) ? v0 : expm1f(v0);
                    v1 = (v1 > 0.f) ? v1 : expm1f(v1);
                }
                if (DO_H16) {
                    if (c + 1 < N)
                        *(__half2*)(C16 + (size_t)r * N + c) = __floats2half2_rn(v0, v1);
                    else if (c < N)
                        C16[(size_t)r * N + c] = __float2half(v0);
                } else {
                    if (c + 1 < N) {
                        float2 st; st.x = v0; st.y = v1;
                        *(float2*)(C + (size_t)r * N + c) = st;
                    } else if (c < N) {
                        C[(size_t)r * N + c] = v0;
                    }
                }
            }
        }
    }
}

// ---------------- fp32 -> fp16 convert ----------------
__global__ void f2h_kernel(const float* __restrict__ in,
                           __half* __restrict__ out, long long n4)
{
    long long i = (long long)blockIdx.x * 256 + threadIdx.x;
    if (i >= n4) return;
    float4 v = *(const float4*)(in + i * 4);
    __half2 h01 = __floats2half2_rn(v.x, v.y);
    __half2 h23 = __floats2half2_rn(v.z, v.w);
    uint2 st;
    st.x = *(uint32_t*)&h01;
    st.y = *(uint32_t*)&h23;
    *(uint2*)(out + i * 4) = st;
}

// ---------------- B permutation to fp16 fragment order ----------------
__global__ void perm_bh_kernel(const float* __restrict__ src, __half* __restrict__ dst,
                               int K, int N, int KB, int NB, int ld, int trans)
{
    int Kp = KB * 32, Np = NB * 128;
    long long i = (long long)blockIdx.x * 256 + threadIdx.x;
    if (i >= (long long)Kp * Np) return;
    int k = (int)(i / Np);
    int n = (int)(i % Np);
    float v = 0.f;
    if (k < K && n < N)
        v = trans ? src[(size_t)n * ld + k] : src[(size_t)k * ld + n];
    int kt = k >> 5, kr = k & 31;
    int ks = kr >> 4, kq = kr & 15;
    int reg = kq >> 3, kb = kq & 7;
    int lc = kb >> 1, h = kb & 1;
    int nb = n >> 7, nr = n & 127;
    int tjj = nr >> 3, lr = nr & 7;
    int lane = lr * 4 + lc;
    size_t off = ((size_t)nb * KB + kt) * 4096 + (ks << 11) + (tjj << 7) + (lane << 2) + (reg << 1) + h;
    dst[off] = __float2half(v);
}

// ---------------- other prep ----------------
__global__ void transpose_kernel(const float* __restrict__ in,
                                 float* __restrict__ out, int R, int C)
{
    __shared__ float t[32][33];
    int c = blockIdx.x * 32 + threadIdx.x;
    int r = blockIdx.y * 32 + threadIdx.y;
    if (r < R && c < C) t[threadIdx.y][threadIdx.x] = in[r * C + c];
    __syncthreads();
    int r2 = blockIdx.x * 32 + threadIdx.y;
    int c2 = blockIdx.y * 32 + threadIdx.x;
    if (r2 < C && c2 < R) out[r2 * R + c2] = t[threadIdx.x][threadIdx.y];
}

__global__ void bias_fuse_kernel(const float* __restrict__ b_enc,
                                 const float* __restrict__ W1,
                                 float* __restrict__ bfused)
{
    int n = blockIdx.x * 128 + threadIdx.x;
    if (n >= HID) return;
    float s = 0.f;
    for (int k = 0; k < DDIM; k++) s += b_enc[k] * W1[(size_t)k * HID + n];
    bfused[n] = s;
}

// ---------------- fused head ----------------
#define HEAD_SMEM ((OUTD*HID + OUTD*PREDD + PREDD)*4)
__global__ __launch_bounds__(256) void h2px3_kernel(
    const float* __restrict__ h1, const float* __restrict__ W2T,
    const float* __restrict__ Wp, const float* __restrict__ bp,
    float* __restrict__ h2, float* __restrict__ logp, float* __restrict__ x3)
{
    extern __shared__ float sw[];
    float* w   = sw;
    float* wp  = sw + OUTD * HID;
    float* bps = wp + OUTD * PREDD;
    const int tid = threadIdx.x;
    for (int i = tid; i < OUTD * HID; i += 256) w[i] = W2T[i];
    for (int i = tid; i < OUTD * PREDD; i += 256) wp[i] = Wp[i];
    if (tid < PREDD) bps[tid] = bp[tid];
    __syncthreads();

    const int wid = tid >> 5, lane = tid & 31;
    const int row = blockIdx.x * 8 + wid;
    if (row >= NN) return;

    float h[16];
    const float* hr = h1 + (size_t)row * HID;
    #pragma unroll
    for (int j = 0; j < 16; j++) h[j] = hr[lane + 32 * j];

    float xacc[16];
    #pragma unroll
    for (int j = 0; j < 16; j++) xacc[j] = 0.f;
    float p[PREDD];
    #pragma unroll
    for (int c2 = 0; c2 < PREDD; c2++) p[c2] = bps[c2];

    #pragma unroll
    for (int c = 0; c < OUTD; c++) {
        const float* wc = w + c * HID;
        float wv[16];
        #pragma unroll
        for (int j = 0; j < 16; j++) wv[j] = wc[lane + 32 * j];
        float s = 0.f;
        #pragma unroll
        for (int j = 0; j < 16; j++) s += h[j] * wv[j];
        #pragma unroll
        for (int o = 16; o > 0; o >>= 1) s += __shfl_xor_sync(0xffffffffu, s, o);
        if (lane == c) h2[(size_t)row * OUTD + c] = s;
        #pragma unroll
        for (int j = 0; j < 16; j++) xacc[j] += s * wv[j];
        #pragma unroll
        for (int c2 = 0; c2 < PREDD; c2++) p[c2] += s * wp[c * PREDD + c2];
    }

    float* xr = x3 + (size_t)row * HID;
    #pragma unroll
    for (int j = 0; j < 16; j++) xr[lane + 32 * j] = xacc[j];

    float m = -1e30f;
    #pragma unroll
    for (int c2 = 0; c2 < PREDD; c2++) m = fmaxf(m, p[c2]);
    float sum = 0.f;
    #pragma unroll
    for (int c2 = 0; c2 < PREDD; c2++) sum += expf(p[c2] - m);
    float lse = m + logf(sum);
    #pragma unroll
    for (int c2 = 0; c2 < PREDD; c2++)
        if (lane == c2) logp[(size_t)row * PREDD + c2] = p[c2] - lse;
}

// ---------------- attention logits ----------------
__global__ void row_logits_kernel(const float* __restrict__ x1,
                                  const float* __restrict__ att_s,
                                  const float* __restrict__ att_d,
                                  float* __restrict__ a1s,
                                  float* __restrict__ a1d, int n)
{
    int row = blockIdx.x * 8 + threadIdx.y;
    if (row >= n) return;
    int lane = threadIdx.x;
    float s = 0.f, d = 0.f;
    const float* xr = x1 + (size_t)row * HID;
    #pragma unroll 4
    for (int k = lane; k < HID; k += 32) {
        float v = xr[k];
        s += v * att_s[k];
        d += v * att_d[k];
    }
    #pragma unroll
    for (int o = 16; o > 0; o >>= 1) {
        s += __shfl_down_sync(0xffffffffu, s, o);
        d += __shfl_down_sync(0xffffffffu, d, o);
    }
    if (lane == 0) { a1s[row] = s; a1d[row] = d; }
}

// ---------------- aggregation with inline softmax + ELU ----------------
__global__ __launch_bounds__(128) void agg_elu_kernel(
    const float* __restrict__ x, const int* __restrict__ src,
    const float* __restrict__ a1s, const float* __restrict__ a1d,
    float* __restrict__ out_f, __half* __restrict__ out_h)
{
    int i = blockIdx.x;
    __shared__ int   ss[DEG];
    __shared__ float se[DEG];
    __shared__ float sa[DEG];
    if (threadIdx.x < DEG) {
        int sj = src[i * DEG + threadIdx.x];
        ss[threadIdx.x] = sj;
        float v = a1s[sj] + a1d[i];
        se[threadIdx.x] = (v > 0.f) ? v : NEG_SLOPE * v;
    }
    __syncthreads();
    if (threadIdx.x == 0) {
        float m = -1e30f;
        #pragma unroll
        for (int j = 0; j < DEG; j++) m = fmaxf(m, se[j]);
        float e[DEG], sum = 0.f;
        #pragma unroll
        for (int j = 0; j < DEG; j++) { e[j] = __expf(se[j] - m); sum += e[j]; }
        float inv = 1.f / sum;
        #pragma unroll
        for (int j = 0; j < DEG; j++) sa[j] = e[j] * inv;
    }
    __syncthreads();
    int c0 = threadIdx.x * 4;
    float a0 = 0.f, a1 = 0.f, a2 = 0.f, a3 = 0.f;
    #pragma unroll
    for (int j = 0; j < DEG; j++) {
        const float4 v = *(const float4*)&x[(size_t)ss[j] * HID + c0];
        float a = sa[j];
        a0 += a * v.x; a1 += a * v.y; a2 += a * v.z; a3 += a * v.w;
    }
    float4 r;
    r.x = (a0 > 0.f) ? a0 : expm1f(a0);
    r.y = (a1 > 0.f) ? a1 : expm1f(a1);
    r.z = (a2 > 0.f) ? a2 : expm1f(a2);
    r.w = (a3 > 0.f) ? a3 : expm1f(a3);
    if (out_f) *(float4*)&out_f[(size_t)i * HID + c0] = r;
    if (out_h) {
        __half2 h01 = __floats2half2_rn(r.x, r.y);
        __half2 h23 = __floats2half2_rn(r.z, r.w);
        uint2 st;
        st.x = *(uint32_t*)&h01;
        st.y = *(uint32_t*)&h23;
        *(uint2*)&out_h[(size_t)i * HID + c0] = st;
    }
}

// ---------------- launch ----------------
static inline dim3 h16_grid(int M, int NB) {
    return dim3(NB, (M + 127) / 128);
}

extern "C" void kernel_launch(void* const* d_in, const int* in_sizes, int n_in,
                              void* d_out, int out_size)
{
    const float* features = (const float*)d_in[0];
    const int*   edge     = (const int*)  d_in[1];
    const float* W_enc    = (const float*)d_in[2];
    const float* b_enc    = (const float*)d_in[3];
    const float* W1       = (const float*)d_in[4];
    const float* att_src  = (const float*)d_in[5];
    const float* att_dst  = (const float*)d_in[6];
    const float* W2       = (const float*)d_in[7];
    const float* W_pred   = (const float*)d_in[8];
    const float* b_pred   = (const float*)d_in[9];
    const float* W_dec    = (const float*)d_in[10];
    const float* b_dec    = (const float*)d_in[11];

    const int* src = edge;

    float* out  = (float*)d_out;
    float* h2   = out;
    float* outm = out + (size_t)NN * OUTD;
    float* logp = out + (size_t)NN * OUTD + (size_t)NN * IN_DIM;

    float *x1, *h1, *x3, *a1s, *a1d, *W2T, *bfused, *Wfused_r;
    __half *feat_h, *Wenc_h, *h3_h, *h4_h, *W1_ph, *W1T_ph, *Wdec_ph, *Wfused_ph;
    cudaGetSymbolAddress((void**)&x1,    g_x1);
    cudaGetSymbolAddress((void**)&h1,    g_h1);
    cudaGetSymbolAddress((void**)&x3,    g_x3);
    cudaGetSymbolAddress((void**)&a1s,   g_a1s);
    cudaGetSymbolAddress((void**)&a1d,   g_a1d);
    cudaGetSymbolAddress((void**)&W2T,   g_W2T);
    cudaGetSymbolAddress((void**)&bfused,   g_bfused);
    cudaGetSymbolAddress((void**)&Wfused_r, g_Wfused_r);
    cudaGetSymbolAddress((void**)&feat_h,   g_feat_h);
    cudaGetSymbolAddress((void**)&Wenc_h,   g_Wenc_h);
    cudaGetSymbolAddress((void**)&h3_h,     g_h3_h);
    cudaGetSymbolAddress((void**)&h4_h,     g_h4_h);
    cudaGetSymbolAddress((void**)&W1_ph,    g_W1_ph);
    cudaGetSymbolAddress((void**)&W1T_ph,   g_W1T_ph);
    cudaGetSymbolAddress((void**)&Wdec_ph,  g_Wdec_ph);
    cudaGetSymbolAddress((void**)&Wfused_ph, g_Wfused_ph);

    static int attr_set = 0;
    if (!attr_set) {
        cudaFuncSetAttribute(h16_gemm_kernel<0>,
            cudaFuncAttributeMaxDynamicSharedMemorySize, GSMEM_BYTES);
        cudaFuncSetAttribute(h16_gemm_kernel<3>,
            cudaFuncAttributeMaxDynamicSharedMemorySize, GSMEM_BYTES);
        cudaFuncSetAttribute(h2px3_kernel,
            cudaFuncAttributeMaxDynamicSharedMemorySize, HEAD_SMEM);
        attr_set = 1;
    }

    // ---- prep ----
    f2h_kernel<<<(int)(((long long)NN*IN_DIM/4 + 255)/256), 256>>>(features, feat_h, (long long)NN*IN_DIM/4);
    f2h_kernel<<<(IN_DIM*DDIM/4 + 255)/256, 256>>>(W_enc, Wenc_h, IN_DIM*DDIM/4);
    perm_bh_kernel<<<(512*512 + 255)/256, 256>>>(W1, W1_ph, DDIM, HID, 16, 4, HID, 0);
    perm_bh_kernel<<<(512*512 + 255)/256, 256>>>(W1, W1T_ph, HID, DDIM, 16, 4, HID, 1);
    bias_fuse_kernel<<<(HID + 127)/128, 128>>>(b_enc, W1, bfused);
    // Wfused = W_enc @ W1  [3000,512] K=512 (fp32 out)
    h16_gemm_kernel<0><<<h16_grid(IN_DIM, 4), 128, GSMEM_BYTES>>>(
        Wenc_h, W1_ph, nullptr, Wfused_r, nullptr, IN_DIM, HID, DDIM, 16);
    perm_bh_kernel<<<(3008*512 + 255)/256, 256>>>(Wfused_r, Wfused_ph, IN_DIM, HID, 94, 4, HID, 0);
    // x1 = features @ Wfused + bfused   [30000,512] K=3000
    h16_gemm_kernel<0><<<h16_grid(NN, 4), 128, GSMEM_BYTES>>>(
        feat_h, Wfused_ph, bfused, x1, nullptr, NN, HID, IN_DIM, 94);

    perm_bh_kernel<<<(512*3072 + 255)/256, 256>>>(W_dec, Wdec_ph, DDIM, IN_DIM, 16, 24, IN_DIM, 0);
    transpose_kernel<<<dim3((OUTD + 31)/32, (HID + 31)/32), dim3(32, 32)>>>(W2, W2T, HID, OUTD);

    // graph pipeline
    row_logits_kernel<<<(NN + 7)/8, dim3(32, 8)>>>(x1, att_src, att_dst, a1s, a1d, NN);
    agg_elu_kernel<<<NN, 128>>>(x1, src, a1s, a1d, h1, nullptr);
    h2px3_kernel<<<(NN + 7)/8, 256, HEAD_SMEM>>>(h1, W2T, W_pred, b_pred, h2, logp, x3);
    agg_elu_kernel<<<NN, 128>>>(x3, src, a1s, a1d, nullptr, h3_h);
    // h4_h = elu(h3 @ W1^T)  [30000,512] K=512, fp16 out
    h16_gemm_kernel<3><<<h16_grid(NN, 4), 128, GSMEM_BYTES>>>(
        h3_h, W1T_ph, nullptr, nullptr, h4_h, NN, DDIM, HID, 16);
    // out = h4 @ W_dec + b_dec  [30000,3000] K=512
    h16_gemm_kernel<0><<<h16_grid(NN, 24), 128, GSMEM_BYTES>>>(
        h4_h, Wdec_ph, b_dec, outm, nullptr, NN, IN_DIM, DDIM, 16);
}

// round 17
// speedup vs baseline: 1.5042x; 1.0121x over previous
#include <cuda_runtime.h>
#include <cuda_fp16.h>
#include <math.h>
#include <stdint.h>

// ---------------- problem constants ----------------
#define NN      30000
#define IN_DIM  3000
#define DDIM    512
#define HID     512
#define OUTD    30
#define PREDD   20
#define DEG     10
#define EDGES   (NN*DEG)
#define NEG_SLOPE 0.2f

// ---------------- scratch ----------------
__device__ float  g_x1 [NN*HID];
__device__ float  g_h1 [NN*HID];
__device__ float  g_x3 [NN*HID];
__device__ float  g_a1s[NN];
__device__ float  g_a1d[NN];
__device__ float  g_W2T[OUTD*HID];
__device__ float  g_bfused[HID];
__device__ float  g_Wfused_r[IN_DIM*HID];
__device__ __half g_feat_h[(size_t)NN*IN_DIM];
__device__ __half g_Wenc_h[IN_DIM*DDIM];
__device__ __half g_h3_h [NN*HID];
__device__ __half g_h4_h [NN*DDIM];
// fragment-permuted fp16 B tiles: [NB][KB][4096 halves] (tile = 32K x 128N)
__device__ __half g_W1_ph    [16*4 *4096];
__device__ __half g_W1T_ph   [16*4 *4096];
__device__ __half g_Wdec_ph  [16*24*4096];
__device__ __half g_Wfused_ph[94*4 *4096];

// =====================================================================
// FP16 tensor-core GEMM: C[M,N] = A[M,K](fp16) @ B(perm fp16) (+bias)
// CTA 128x128, BK=64 (4 x k16), 4 warps (2x2), warp tile 64x64.
// A fragments via ldmatrix.m8n8.x4 (1 issue per 16x16 fragment).
// A smem rows padded to 72 halves (144B): ldmatrix phases hit all 32 banks.
// B smem: contiguous fragment-order tiles, uint2 loads conflict-free.
// 3-stage cp.async.cg, 1 sync per 64-k iteration.
// FLAGS bit0 = ELU, bit1 = fp16 output (C16).
// =====================================================================
#define HA_ROWB   144
#define A_STAGE_B (128*HA_ROWB)         // 18432
#define B_STAGE_B 16384
#define STAGE_B   (A_STAGE_B + B_STAGE_B)
#define STAGES    3
#define GSMEM_BYTES (STAGES*STAGE_B)    // 104448

__device__ __forceinline__ void cp16cg(uint32_t dst, const void* src, int sz) {
    asm volatile("cp.async.cg.shared.global [%0], [%1], 16, %2;\n"
                 :: "r"(dst), "l"(src), "r"(sz));
}

template<int FLAGS>
__global__ __launch_bounds__(128, 2) void h16_gemm_kernel(
    const __half* __restrict__ A, const __half* __restrict__ Bp,
    const float* __restrict__ bias, float* __restrict__ C,
    __half* __restrict__ C16, int M, int N, int K, int KB)
{
    extern __shared__ char sm[];
    const uint32_t smb = (uint32_t)__cvta_generic_to_shared(sm);

    const int tid  = threadIdx.x;
    const int lane = tid & 31;
    const int warp = tid >> 5;
    const int wm   = warp >> 1;
    const int wn   = warp & 1;
    const int row0 = blockIdx.y * 128;
    const int col0 = blockIdx.x * 128;
    const int lr   = lane >> 2;
    const int lc   = lane & 3;
    // ldmatrix per-lane addressing: row offset + k-byte offset
    const int lm_row = (lane & 7) + ((lane >> 3) & 1) * 8;  // 0..15
    const int lm_kb  = (lane >> 4) * 16;                    // 0 or 16 bytes

    float acc[4][8][4];
    #pragma unroll
    for (int i = 0; i < 4; i++)
        #pragma unroll
        for (int j = 0; j < 8; j++)
            #pragma unroll
            for (int q = 0; q < 4; q++) acc[i][j][q] = 0.f;

    const int nk2 = KB >> 1;
    const __half* Btiles = Bp + (size_t)blockIdx.x * KB * 4096;

    auto load_tile = [&](int stage, int t) {
        const int k0 = t << 6;
        const uint32_t Asb = smb + stage * STAGE_B;
        const uint32_t Bsb = Asb + A_STAGE_B;
        #pragma unroll
        for (int it = 0; it < 8; it++) {
            int idx = tid + it * 128;
            int r = idx >> 3, ch = idx & 7;
            int gr = row0 + r, gc = k0 + ch * 8;
            int sz = (gr < M && gc < K) ? 16 : 0;
            cp16cg(Asb + r * HA_ROWB + ch * 16, A + (size_t)gr * K + gc, sz);
        }
        const __half* Bt = Btiles + (size_t)t * 8192;
        #pragma unroll
        for (int it = 0; it < 8; it++) {
            int cb = (tid + it * 128) << 4;
            cp16cg(Bsb + cb, (const char*)Bt + cb, 16);
        }
    };

    load_tile(0, 0);
    asm volatile("cp.async.commit_group;\n");
    if (nk2 > 1) load_tile(1, 1);
    asm volatile("cp.async.commit_group;\n");

    int stage = 0;
    for (int t = 0; t < nk2; t++) {
        asm volatile("cp.async.wait_group 1;\n");
        __syncthreads();

        if (t + 2 < nk2) load_tile((stage + 2 >= STAGES) ? stage + 2 - STAGES : stage + 2, t + 2);
        asm volatile("cp.async.commit_group;\n");

        const uint32_t AsmB = smb + stage * STAGE_B;
        const char*    Bsb  = sm + stage * STAGE_B + A_STAGE_B;
        // per-thread ldmatrix base for this stage (row part fixed per ti below)
        const uint32_t lmBase = AsmB + (wm * 64 + lm_row) * HA_ROWB + lm_kb;

        #pragma unroll
        for (int ks = 0; ks < 4; ks++) {
            uint32_t a[4][4];
            uint2 b[8];
            #pragma unroll
            for (int ti = 0; ti < 4; ti++) {
                uint32_t addr = lmBase + ti * (16 * HA_ROWB) + ks * 32;
                asm volatile(
                    "ldmatrix.sync.aligned.m8n8.x4.shared.b16 {%0,%1,%2,%3}, [%4];"
                    : "=r"(a[ti][0]), "=r"(a[ti][1]), "=r"(a[ti][2]), "=r"(a[ti][3])
                    : "r"(addr));
            }
            #pragma unroll
            for (int tj = 0; tj < 8; tj++) {
                int tjj = wn * 8 + tj;
                b[tj] = *(const uint2*)(Bsb + ks * 4096 + tjj * 256 + lane * 8);
            }
            #pragma unroll
            for (int ti = 0; ti < 4; ti++)
                #pragma unroll
                for (int tj = 0; tj < 8; tj++) {
                    asm volatile(
                        "mma.sync.aligned.m16n8k16.row.col.f32.f16.f16.f32 "
                        "{%0,%1,%2,%3}, {%4,%5,%6,%7}, {%8,%9}, {%0,%1,%2,%3};\n"
                        : "+f"(acc[ti][tj][0]), "+f"(acc[ti][tj][1]),
                          "+f"(acc[ti][tj][2]), "+f"(acc[ti][tj][3])
                        : "r"(a[ti][0]), "r"(a[ti][1]), "r"(a[ti][2]), "r"(a[ti][3]),
                          "r"(b[tj].x), "r"(b[tj].y));
                }
        }
        stage = (stage + 1 >= STAGES) ? 0 : stage + 1;
    }

    constexpr bool DO_ELU = (FLAGS & 1) != 0;
    constexpr bool DO_H16 = (FLAGS & 2) != 0;
    #pragma unroll
    for (int ti = 0; ti < 4; ti++) {
        int r0 = row0 + wm * 64 + ti * 16 + lr;
        int r1 = r0 + 8;
        #pragma unroll
        for (int tj = 0; tj < 8; tj++) {
            int c = col0 + wn * 64 + tj * 8 + (lc << 1);
            float bv0 = 0.f, bv1 = 0.f;
            if (bias && c + 1 < N) {
                float2 bv = *(const float2*)(bias + c);
                bv0 = bv.x; bv1 = bv.y;
            } else if (bias && c < N) bv0 = bias[c];
            #pragma unroll
            for (int h = 0; h < 2; h++) {
                int r = h ? r1 : r0;
                if (r >= M) continue;
                float v0 = acc[ti][tj][h*2+0] + bv0;
                float v1 = acc[ti][tj][h*2+1] + bv1;
                if (DO_ELU) {
                    v0 = (v0 > 0.f) ? v0 : expm1f(v0);
                    v1 = (v1 > 0.f) ? v1 : expm1f(v1);
                }
                if (DO_H16) {
                    if (c + 1 < N)
                        *(__half2*)(C16 + (size_t)r * N + c) = __floats2half2_rn(v0, v1);
                    else if (c < N)
                        C16[(size_t)r * N + c] = __float2half(v0);
                } else {
                    if (c + 1 < N) {
                        float2 st; st.x = v0; st.y = v1;
                        *(float2*)(C + (size_t)r * N + c) = st;
                    } else if (c < N) {
                        C[(size_t)r * N + c] = v0;
                    }
                }
            }
        }
    }
}

// ---------------- fp32 -> fp16 convert ----------------
__global__ void f2h_kernel(const float* __restrict__ in,
                           __half* __restrict__ out, long long n4)
{
    long long i = (long long)blockIdx.x * 256 + threadIdx.x;
    if (i >= n4) return;
    float4 v = *(const float4*)(in + i * 4);
    __half2 h01 = __floats2half2_rn(v.x, v.y);
    __half2 h23 = __floats2half2_rn(v.z, v.w);
    uint2 st;
    st.x = *(uint32_t*)&h01;
    st.y = *(uint32_t*)&h23;
    *(uint2*)(out + i * 4) = st;
}

// ---------------- B permutation to fp16 fragment order ----------------
__global__ void perm_bh_kernel(const float* __restrict__ src, __half* __restrict__ dst,
                               int K, int N, int KB, int NB, int ld, int trans)
{
    int Kp = KB * 32, Np = NB * 128;
    long long i = (long long)blockIdx.x * 256 + threadIdx.x;
    if (i >= (long long)Kp * Np) return;
    int k = (int)(i / Np);
    int n = (int)(i % Np);
    float v = 0.f;
    if (k < K && n < N)
        v = trans ? src[(size_t)n * ld + k] : src[(size_t)k * ld + n];
    int kt = k >> 5, kr = k & 31;
    int ks = kr >> 4, kq = kr & 15;
    int reg = kq >> 3, kb = kq & 7;
    int lc = kb >> 1, h = kb & 1;
    int nb = n >> 7, nr = n & 127;
    int tjj = nr >> 3, lr = nr & 7;
    int lane = lr * 4 + lc;
    size_t off = ((size_t)nb * KB + kt) * 4096 + (ks << 11) + (tjj << 7) + (lane << 2) + (reg << 1) + h;
    dst[off] = __float2half(v);
}

// ---------------- other prep ----------------
__global__ void transpose_kernel(const float* __restrict__ in,
                                 float* __restrict__ out, int R, int C)
{
    __shared__ float t[32][33];
    int c = blockIdx.x * 32 + threadIdx.x;
    int r = blockIdx.y * 32 + threadIdx.y;
    if (r < R && c < C) t[threadIdx.y][threadIdx.x] = in[r * C + c];
    __syncthreads();
    int r2 = blockIdx.x * 32 + threadIdx.y;
    int c2 = blockIdx.y * 32 + threadIdx.x;
    if (r2 < C && c2 < R) out[r2 * R + c2] = t[threadIdx.x][threadIdx.y];
}

__global__ void bias_fuse_kernel(const float* __restrict__ b_enc,
                                 const float* __restrict__ W1,
                                 float* __restrict__ bfused)
{
    int n = blockIdx.x * 128 + threadIdx.x;
    if (n >= HID) return;
    float s = 0.f;
    for (int k = 0; k < DDIM; k++) s += b_enc[k] * W1[(size_t)k * HID + n];
    bfused[n] = s;
}

// ---------------- fused head ----------------
#define HEAD_SMEM ((OUTD*HID + OUTD*PREDD + PREDD)*4)
__global__ __launch_bounds__(256) void h2px3_kernel(
    const float* __restrict__ h1, const float* __restrict__ W2T,
    const float* __restrict__ Wp, const float* __restrict__ bp,
    float* __restrict__ h2, float* __restrict__ logp, float* __restrict__ x3)
{
    extern __shared__ float sw[];
    float* w   = sw;
    float* wp  = sw + OUTD * HID;
    float* bps = wp + OUTD * PREDD;
    const int tid = threadIdx.x;
    for (int i = tid; i < OUTD * HID; i += 256) w[i] = W2T[i];
    for (int i = tid; i < OUTD * PREDD; i += 256) wp[i] = Wp[i];
    if (tid < PREDD) bps[tid] = bp[tid];
    __syncthreads();

    const int wid = tid >> 5, lane = tid & 31;
    const int row = blockIdx.x * 8 + wid;
    if (row >= NN) return;

    float h[16];
    const float* hr = h1 + (size_t)row * HID;
    #pragma unroll
    for (int j = 0; j < 16; j++) h[j] = hr[lane + 32 * j];

    float xacc[16];
    #pragma unroll
    for (int j = 0; j < 16; j++) xacc[j] = 0.f;
    float p[PREDD];
    #pragma unroll
    for (int c2 = 0; c2 < PREDD; c2++) p[c2] = bps[c2];

    #pragma unroll
    for (int c = 0; c < OUTD; c++) {
        const float* wc = w + c * HID;
        float wv[16];
        #pragma unroll
        for (int j = 0; j < 16; j++) wv[j] = wc[lane + 32 * j];
        float s = 0.f;
        #pragma unroll
        for (int j = 0; j < 16; j++) s += h[j] * wv[j];
        #pragma unroll
        for (int o = 16; o > 0; o >>= 1) s += __shfl_xor_sync(0xffffffffu, s, o);
        if (lane == c) h2[(size_t)row * OUTD + c] = s;
        #pragma unroll
        for (int j = 0; j < 16; j++) xacc[j] += s * wv[j];
        #pragma unroll
        for (int c2 = 0; c2 < PREDD; c2++) p[c2] += s * wp[c * PREDD + c2];
    }

    float* xr = x3 + (size_t)row * HID;
    #pragma unroll
    for (int j = 0; j < 16; j++) xr[lane + 32 * j] = xacc[j];

    float m = -1e30f;
    #pragma unroll
    for (int c2 = 0; c2 < PREDD; c2++) m = fmaxf(m, p[c2]);
    float sum = 0.f;
    #pragma unroll
    for (int c2 = 0; c2 < PREDD; c2++) sum += expf(p[c2] - m);
    float lse = m + logf(sum);
    #pragma unroll
    for (int c2 = 0; c2 < PREDD; c2++)
        if (lane == c2) logp[(size_t)row * PREDD + c2] = p[c2] - lse;
}

// ---------------- attention logits ----------------
__global__ void row_logits_kernel(const float* __restrict__ x1,
                                  const float* __restrict__ att_s,
                                  const float* __restrict__ att_d,
                                  float* __restrict__ a1s,
                                  float* __restrict__ a1d, int n)
{
    int row = blockIdx.x * 8 + threadIdx.y;
    if (row >= n) return;
    int lane = threadIdx.x;
    float s = 0.f, d = 0.f;
    const float* xr = x1 + (size_t)row * HID;
    #pragma unroll 4
    for (int k = lane; k < HID; k += 32) {
        float v = xr[k];
        s += v * att_s[k];
        d += v * att_d[k];
    }
    #pragma unroll
    for (int o = 16; o > 0; o >>= 1) {
        s += __shfl_down_sync(0xffffffffu, s, o);
        d += __shfl_down_sync(0xffffffffu, d, o);
    }
    if (lane == 0) { a1s[row] = s; a1d[row] = d; }
}

// ---------------- aggregation with inline softmax + ELU ----------------
__global__ __launch_bounds__(128) void agg_elu_kernel(
    const float* __restrict__ x, const int* __restrict__ src,
    const float* __restrict__ a1s, const float* __restrict__ a1d,
    float* __restrict__ out_f, __half* __restrict__ out_h)
{
    int i = blockIdx.x;
    __shared__ int   ss[DEG];
    __shared__ float se[DEG];
    __shared__ float sa[DEG];
    if (threadIdx.x < DEG) {
        int sj = src[i * DEG + threadIdx.x];
        ss[threadIdx.x] = sj;
        float v = a1s[sj] + a1d[i];
        se[threadIdx.x] = (v > 0.f) ? v : NEG_SLOPE * v;
    }
    __syncthreads();
    if (threadIdx.x == 0) {
        float m = -1e30f;
        #pragma unroll
        for (int j = 0; j < DEG; j++) m = fmaxf(m, se[j]);
        float e[DEG], sum = 0.f;
        #pragma unroll
        for (int j = 0; j < DEG; j++) { e[j] = __expf(se[j] - m); sum += e[j]; }
        float inv = 1.f / sum;
        #pragma unroll
        for (int j = 0; j < DEG; j++) sa[j] = e[j] * inv;
    }
    __syncthreads();
    int c0 = threadIdx.x * 4;
    float a0 = 0.f, a1 = 0.f, a2 = 0.f, a3 = 0.f;
    #pragma unroll
    for (int j = 0; j < DEG; j++) {
        const float4 v = *(const float4*)&x[(size_t)ss[j] * HID + c0];
        float a = sa[j];
        a0 += a * v.x; a1 += a * v.y; a2 += a * v.z; a3 += a * v.w;
    }
    float4 r;
    r.x = (a0 > 0.f) ? a0 : expm1f(a0);
    r.y = (a1 > 0.f) ? a1 : expm1f(a1);
    r.z = (a2 > 0.f) ? a2 : expm1f(a2);
    r.w = (a3 > 0.f) ? a3 : expm1f(a3);
    if (out_f) *(float4*)&out_f[(size_t)i * HID + c0] = r;
    if (out_h) {
        __half2 h01 = __floats2half2_rn(r.x, r.y);
        __half2 h23 = __floats2half2_rn(r.z, r.w);
        uint2 st;
        st.x = *(uint32_t*)&h01;
        st.y = *(uint32_t*)&h23;
        *(uint2*)&out_h[(size_t)i * HID + c0] = st;
    }
}

// ---------------- launch ----------------
static inline dim3 h16_grid(int M, int NB) {
    return dim3(NB, (M + 127) / 128);
}

extern "C" void kernel_launch(void* const* d_in, const int* in_sizes, int n_in,
                              void* d_out, int out_size)
{
    const float* features = (const float*)d_in[0];
    const int*   edge     = (const int*)  d_in[1];
    const float* W_enc    = (const float*)d_in[2];
    const float* b_enc    = (const float*)d_in[3];
    const float* W1       = (const float*)d_in[4];
    const float* att_src  = (const float*)d_in[5];
    const float* att_dst  = (const float*)d_in[6];
    const float* W2       = (const float*)d_in[7];
    const float* W_pred   = (const float*)d_in[8];
    const float* b_pred   = (const float*)d_in[9];
    const float* W_dec    = (const float*)d_in[10];
    const float* b_dec    = (const float*)d_in[11];

    const int* src = edge;

    float* out  = (float*)d_out;
    float* h2   = out;
    float* outm = out + (size_t)NN * OUTD;
    float* logp = out + (size_t)NN * OUTD + (size_t)NN * IN_DIM;

    float *x1, *h1, *x3, *a1s, *a1d, *W2T, *bfused, *Wfused_r;
    __half *feat_h, *Wenc_h, *h3_h, *h4_h, *W1_ph, *W1T_ph, *Wdec_ph, *Wfused_ph;
    cudaGetSymbolAddress((void**)&x1,    g_x1);
    cudaGetSymbolAddress((void**)&h1,    g_h1);
    cudaGetSymbolAddress((void**)&x3,    g_x3);
    cudaGetSymbolAddress((void**)&a1s,   g_a1s);
    cudaGetSymbolAddress((void**)&a1d,   g_a1d);
    cudaGetSymbolAddress((void**)&W2T,   g_W2T);
    cudaGetSymbolAddress((void**)&bfused,   g_bfused);
    cudaGetSymbolAddress((void**)&Wfused_r, g_Wfused_r);
    cudaGetSymbolAddress((void**)&feat_h,   g_feat_h);
    cudaGetSymbolAddress((void**)&Wenc_h,   g_Wenc_h);
    cudaGetSymbolAddress((void**)&h3_h,     g_h3_h);
    cudaGetSymbolAddress((void**)&h4_h,     g_h4_h);
    cudaGetSymbolAddress((void**)&W1_ph,    g_W1_ph);
    cudaGetSymbolAddress((void**)&W1T_ph,   g_W1T_ph);
    cudaGetSymbolAddress((void**)&Wdec_ph,  g_Wdec_ph);
    cudaGetSymbolAddress((void**)&Wfused_ph, g_Wfused_ph);

    static int attr_set = 0;
    if (!attr_set) {
        cudaFuncSetAttribute(h16_gemm_kernel<0>,
            cudaFuncAttributeMaxDynamicSharedMemorySize, GSMEM_BYTES);
        cudaFuncSetAttribute(h16_gemm_kernel<3>,
            cudaFuncAttributeMaxDynamicSharedMemorySize, GSMEM_BYTES);
        cudaFuncSetAttribute(h2px3_kernel,
            cudaFuncAttributeMaxDynamicSharedMemorySize, HEAD_SMEM);
        attr_set = 1;
    }

    // ---- prep ----
    f2h_kernel<<<(int)(((long long)NN*IN_DIM/4 + 255)/256), 256>>>(features, feat_h, (long long)NN*IN_DIM/4);
    f2h_kernel<<<(IN_DIM*DDIM/4 + 255)/256, 256>>>(W_enc, Wenc_h, IN_DIM*DDIM/4);
    perm_bh_kernel<<<(512*512 + 255)/256, 256>>>(W1, W1_ph, DDIM, HID, 16, 4, HID, 0);
    perm_bh_kernel<<<(512*512 + 255)/256, 256>>>(W1, W1T_ph, HID, DDIM, 16, 4, HID, 1);
    bias_fuse_kernel<<<(HID + 127)/128, 128>>>(b_enc, W1, bfused);
    // Wfused = W_enc @ W1  [3000,512] K=512 (fp32 out)
    h16_gemm_kernel<0><<<h16_grid(IN_DIM, 4), 128, GSMEM_BYTES>>>(
        Wenc_h, W1_ph, nullptr, Wfused_r, nullptr, IN_DIM, HID, DDIM, 16);
    perm_bh_kernel<<<(3008*512 + 255)/256, 256>>>(Wfused_r, Wfused_ph, IN_DIM, HID, 94, 4, HID, 0);
    // x1 = features @ Wfused + bfused   [30000,512] K=3000
    h16_gemm_kernel<0><<<h16_grid(NN, 4), 128, GSMEM_BYTES>>>(
        feat_h, Wfused_ph, bfused, x1, nullptr, NN, HID, IN_DIM, 94);

    perm_bh_kernel<<<(512*3072 + 255)/256, 256>>>(W_dec, Wdec_ph, DDIM, IN_DIM, 16, 24, IN_DIM, 0);
    transpose_kernel<<<dim3((OUTD + 31)/32, (HID + 31)/32), dim3(32, 32)>>>(W2, W2T, HID, OUTD);

    // graph pipeline
    row_logits_kernel<<<(NN + 7)/8, dim3(32, 8)>>>(x1, att_src, att_dst, a1s, a1d, NN);
    agg_elu_kernel<<<NN, 128>>>(x1, src, a1s, a1d, h1, nullptr);
    h2px3_kernel<<<(NN + 7)/8, 256, HEAD_SMEM>>>(h1, W2T, W_pred, b_pred, h2, logp, x3);
    agg_elu_kernel<<<NN, 128>>>(x3, src, a1s, a1d, nullptr, h3_h);
    // h4_h = elu(h3 @ W1^T)  [30000,512] K=512, fp16 out
    h16_gemm_kernel<3><<<h16_grid(NN, 4), 128, GSMEM_BYTES>>>(
        h3_h, W1T_ph, nullptr, nullptr, h4_h, NN, DDIM, HID, 16);
    // out = h4 @ W_dec + b_dec  [30000,3000] K=512
    h16_gemm_kernel<0><<<h16_grid(NN, 24), 128, GSMEM_BYTES>>>(
        h4_h, Wdec_ph, b_dec, outm, nullptr, NN, IN_DIM, DDIM, 16);
}